// round 1
// baseline (speedup 1.0000x reference)
#include <cuda_runtime.h>
#include <cstdint>
#include <cstddef>

#define B_    64
#define S_    2048
#define I_    512
#define H_    512
#define NCOL  2560   // 5*H
#define NBLK  128    // persistent blocks, 4 h-columns each

// ---------------- device scratch (no allocations allowed) ----------------
__device__ float    g_xz[335544320];     // [S][B][5H] fp32 = 1.34 GB
__device__ float    g_h[2][B_ * H_];     // ping-pong hidden state
__device__ unsigned g_arrive[NBLK];      // grid-barrier flags

// ---------------- init: zero h0 and barrier flags ----------------
__global__ void init_state() {
    int idx = blockIdx.x * blockDim.x + threadIdx.x;
    if (idx < B_ * H_) g_h[0][idx] = 0.f;
    if (idx < NBLK)    g_arrive[idx] = 0u;
}

// ---------------- precompute: xz = X @ W[:I] + b ----------------
// M = B*S = 131072 (row m' = s*64 + b), N = 2560, K = 512
// classic 128x128x16 SGEMM, thread tile 8x8, 256 threads
__global__ void __launch_bounds__(256, 2)
gemm_precompute(const float* __restrict__ X,
                const float* __restrict__ W,
                const float* __restrict__ bias) {
    __shared__ float As[16][132];   // A^T tile [k][m], padded
    __shared__ float Bs[16][128];   // B tile  [k][n]

    const int tid   = threadIdx.x;
    const int ntile = blockIdx.x * 128;
    const int mtile = blockIdx.y * 128;
    const int tx    = tid & 15;     // col group
    const int ty    = tid >> 4;     // row group

    float acc[8][8];
#pragma unroll
    for (int i = 0; i < 8; ++i)
#pragma unroll
        for (int j = 0; j < 8; ++j) acc[i][j] = 0.f;

    // A-load mapping: 2 float4 per thread
    size_t arow[2]; int ar[2], akc[2];
#pragma unroll
    for (int i = 0; i < 2; ++i) {
        int f  = tid + i * 256;
        int r  = f >> 2;                // 0..127
        int kc = (f & 3) * 4;           // 0,4,8,12
        int mm = mtile + r;             // m' = s*64 + b
        int bb = mm & 63;
        int sA = mm >> 6;
        arow[i] = ((size_t)bb * S_ + sA) * I_ + kc;
        ar[i] = r; akc[i] = kc;
    }
    // B-load mapping: 2 float4 per thread
    size_t baddr[2]; int bkr[2], bnn[2];
#pragma unroll
    for (int i = 0; i < 2; ++i) {
        int f  = tid + i * 256;         // 0..511
        int kr = f >> 5;                // 0..15
        int nn = (f & 31) * 4;          // 0..124
        baddr[i] = (size_t)kr * NCOL + ntile + nn;
        bkr[i] = kr; bnn[i] = nn;
    }

    for (int kt = 0; kt < I_; kt += 16) {
#pragma unroll
        for (int i = 0; i < 2; ++i) {
            float4 v = *reinterpret_cast<const float4*>(&X[arow[i] + kt]);
            As[akc[i] + 0][ar[i]] = v.x;
            As[akc[i] + 1][ar[i]] = v.y;
            As[akc[i] + 2][ar[i]] = v.z;
            As[akc[i] + 3][ar[i]] = v.w;
        }
#pragma unroll
        for (int i = 0; i < 2; ++i) {
            float4 v = *reinterpret_cast<const float4*>(&W[baddr[i] + (size_t)kt * NCOL]);
            *reinterpret_cast<float4*>(&Bs[bkr[i]][bnn[i]]) = v;
        }
        __syncthreads();
#pragma unroll
        for (int k = 0; k < 16; ++k) {
            float a[8], b8[8];
            *reinterpret_cast<float4*>(&a[0])  = *reinterpret_cast<const float4*>(&As[k][ty * 8]);
            *reinterpret_cast<float4*>(&a[4])  = *reinterpret_cast<const float4*>(&As[k][ty * 8 + 4]);
            *reinterpret_cast<float4*>(&b8[0]) = *reinterpret_cast<const float4*>(&Bs[k][tx * 8]);
            *reinterpret_cast<float4*>(&b8[4]) = *reinterpret_cast<const float4*>(&Bs[k][tx * 8 + 4]);
#pragma unroll
            for (int i = 0; i < 8; ++i)
#pragma unroll
                for (int j = 0; j < 8; ++j)
                    acc[i][j] = fmaf(a[i], b8[j], acc[i][j]);
        }
        __syncthreads();
    }

    float bv[8];
#pragma unroll
    for (int j = 0; j < 8; ++j) bv[j] = bias[ntile + tx * 8 + j];

#pragma unroll
    for (int i = 0; i < 8; ++i) {
        size_t row = (size_t)(mtile + ty * 8 + i) * NCOL + ntile + tx * 8;
        float4 o0, o1;
        o0.x = acc[i][0] + bv[0]; o0.y = acc[i][1] + bv[1];
        o0.z = acc[i][2] + bv[2]; o0.w = acc[i][3] + bv[3];
        o1.x = acc[i][4] + bv[4]; o1.y = acc[i][5] + bv[5];
        o1.z = acc[i][6] + bv[6]; o1.w = acc[i][7] + bv[7];
        *reinterpret_cast<float4*>(&g_xz[row])     = o0;
        *reinterpret_cast<float4*>(&g_xz[row + 4]) = o1;
    }
}

// ---------------- persistent recurrent kernel ----------------
// 128 blocks x 256 threads. Block owns h-columns [bid*4, bid*4+4) -> 20 z-cols.
// SMEM: wT[20][516] (resident across steps) + h_sm[64][516] (restaged per step,
// reused as partial buffer p[8][64][20] after compute).
#define WT_STRIDE  516
#define SMEM_FLOATS (20 * WT_STRIDE + 64 * WT_STRIDE)
#define SMEM_BYTES  (SMEM_FLOATS * 4)

__device__ __forceinline__ float sigmoidf_(float x) {
    return 1.f / (1.f + __expf(-x));
}

__global__ void __launch_bounds__(256, 1)
lstm_recurrent(const float* __restrict__ W, float* __restrict__ y) {
    extern __shared__ float sm[];
    float* wT   = sm;                    // [20][516]
    float* h_sm = sm + 20 * WT_STRIDE;   // [64][516]

    const int tid = threadIdx.x;
    const int bid = blockIdx.x;
    const int j0  = bid * 4;

    // load W slice once: wT[c][k] = W[I+k][g*H + j0+jj], c = g*4+jj
    for (int idx = tid; idx < 20 * 512; idx += 256) {
        int c = idx >> 9;
        int k = idx & 511;
        int g = c >> 2, jj = c & 3;
        wT[c * WT_STRIDE + k] = W[(size_t)(I_ + k) * NCOL + g * H_ + j0 + jj];
    }

    // reducer identity: one (b, j) per thread; c-state lives in a register
    const int b_r  = tid >> 2;
    const int jj_r = tid & 3;
    const int j_r  = j0 + jj_r;
    float c_state = 0.f;

    // compute identity: warp = k-slice of 64; lane tile = 8 b x 5 cols
    const int warp = tid >> 5;
    const int lane = tid & 31;
    const int bg   = lane & 7;       // b = bg + 8*i
    const int ng   = lane >> 3;      // cols c = ng*5 .. ng*5+4
    const int kb   = warp * 64;

    const float* wrow[5];
#pragma unroll
    for (int j = 0; j < 5; ++j) wrow[j] = wT + (ng * 5 + j) * WT_STRIDE + kb;

    __syncthreads();

    for (int s = 0; s < S_; ++s) {
        const float* hin  = g_h[s & 1];
        float*       hout = g_h[(s & 1) ^ 1];

        // prefetch xz gate pre-activations (DRAM, hidden behind compute)
        float xzv[5];
        {
            const float* xp = g_xz + ((size_t)s * B_ + b_r) * NCOL + j_r;
#pragma unroll
            for (int g = 0; g < 5; ++g) xzv[g] = __ldg(xp + g * H_);
        }

        // stage h into SMEM (ldcg: other SMs wrote it; L1 may be stale)
        for (int q = tid; q < (B_ * H_) / 4; q += 256) {
            float4 v = __ldcg(reinterpret_cast<const float4*>(hin) + q);
            int b  = q >> 7;
            int k4 = (q & 127) << 2;
            *reinterpret_cast<float4*>(&h_sm[b * WT_STRIDE + k4]) = v;
        }
        __syncthreads();

        // partial GEMM: acc[i][j] = sum_{k in warp slice} h[bg+8i][k] * wT[ng*5+j][k]
        float acc[8][5];
#pragma unroll
        for (int i = 0; i < 8; ++i)
#pragma unroll
            for (int j = 0; j < 5; ++j) acc[i][j] = 0.f;

#pragma unroll 2
        for (int kk = 0; kk < 64; kk += 4) {
            float4 w4[5];
#pragma unroll
            for (int j = 0; j < 5; ++j)
                w4[j] = *reinterpret_cast<const float4*>(wrow[j] + kk);
#pragma unroll
            for (int i = 0; i < 8; ++i) {
                float4 h4 = *reinterpret_cast<const float4*>(
                    &h_sm[(bg + 8 * i) * WT_STRIDE + kb + kk]);
#pragma unroll
                for (int j = 0; j < 5; ++j) {
                    acc[i][j] = fmaf(h4.x, w4[j].x, acc[i][j]);
                    acc[i][j] = fmaf(h4.y, w4[j].y, acc[i][j]);
                    acc[i][j] = fmaf(h4.z, w4[j].z, acc[i][j]);
                    acc[i][j] = fmaf(h4.w, w4[j].w, acc[i][j]);
                }
            }
        }
        __syncthreads();

        // spill partials (reuse h_sm): p[warp][b][c]
        float* p = h_sm;
#pragma unroll
        for (int i = 0; i < 8; ++i)
#pragma unroll
            for (int j = 0; j < 5; ++j)
                p[warp * 1280 + (bg + 8 * i) * 20 + ng * 5 + j] = acc[i][j];
        __syncthreads();

        // reduce 8 warp partials + xz, then gates
        float z[5];
#pragma unroll
        for (int g = 0; g < 5; ++g) {
            float t = xzv[g];
            const float* pp = p + b_r * 20 + g * 4 + jj_r;
#pragma unroll
            for (int w = 0; w < 8; ++w) t += pp[w * 1280];
            z[g] = t;
        }
        float it = sigmoidf_(z[0]);
        float ft = sigmoidf_(z[1]);
        float ot = sigmoidf_(z[2]);
        float tc = tanhf(z[3]);
        float dt = tanhf(z[4]);
        float cp = ft * c_state + it * tc;
        float cn = cp + dt * (cp - c_state);   // highway update
        c_state = cn;
        float hn = ot * tanhf(cn);

        hout[b_r * H_ + j_r] = hn;
        y[((size_t)b_r * S_ + s) * H_ + j_r] = hn;

        // ---- grid barrier (flag array; all 128 CTAs co-resident) ----
        __threadfence();
        __syncthreads();
        if (tid == 0)
            *reinterpret_cast<volatile unsigned*>(&g_arrive[bid]) = (unsigned)(s + 1);
        if (tid < NBLK) {
            while (*reinterpret_cast<volatile unsigned*>(&g_arrive[tid]) < (unsigned)(s + 1)) {
                __nanosleep(32);
            }
        }
        __threadfence();
        __syncthreads();
    }
}

// ---------------- launch ----------------
extern "C" void kernel_launch(void* const* d_in, const int* in_sizes, int n_in,
                              void* d_out, int out_size) {
    const float* x    = (const float*)d_in[0];  // [B,S,I]
    const float* W    = (const float*)d_in[1];  // [I+H, 5H]
    const float* bias = (const float*)d_in[2];  // [5H]
    float* y = (float*)d_out;                   // [B,S,H]

    cudaFuncSetAttribute(lstm_recurrent,
                         cudaFuncAttributeMaxDynamicSharedMemorySize, SMEM_BYTES);

    init_state<<<128, 256>>>();

    dim3 grid(NCOL / 128, (B_ * S_) / 128);     // (20, 1024)
    gemm_precompute<<<grid, 256>>>(x, W, bias);

    lstm_recurrent<<<NBLK, 256, SMEM_BYTES>>>(W, y);
}

// round 3
// speedup vs baseline: 1.3079x; 1.3079x over previous
#include <cuda_runtime.h>
#include <cuda_bf16.h>
#include <cstdint>
#include <cstddef>

#define B_    64
#define S_    2048
#define I_    512
#define H_    512
#define NCOL  2560   // 5*H
#define NBLK  128    // persistent blocks for recurrence

// ---------------- device scratch (no allocations allowed) ----------------
__device__ float          g_xz[335544320];       // [S*B][5H] fp32
__device__ __nv_bfloat16  g_hb[2][2][B_ * H_];   // [pingpong][hi/lo][b*512+j]
__device__ unsigned       g_arrive[NBLK];        // grid-barrier flags
__device__ __nv_bfloat16  g_xhi[67108864];       // [S*B][512] bf16 hi
__device__ __nv_bfloat16  g_xlo[67108864];       // [S*B][512] bf16 lo
__device__ __nv_bfloat16  g_wthi[NCOL * 512];    // W[0:512][:] transposed [n][k]
__device__ __nv_bfloat16  g_wtlo[NCOL * 512];

// ---------------- PTX helpers (baseline PTX only, no sm_103a features) ----
__device__ __forceinline__ uint32_t smem_u32(const void* p) {
    uint32_t a;
    asm("{ .reg .u64 t; cvta.to.shared.u64 t, %1; cvt.u32.u64 %0, t; }" : "=r"(a) : "l"(p));
    return a;
}
__device__ __forceinline__ void ldmx4(uint32_t* r, uint32_t addr) {
    asm volatile("ldmatrix.sync.aligned.m8n8.x4.shared.b16 {%0,%1,%2,%3}, [%4];"
                 : "=r"(r[0]), "=r"(r[1]), "=r"(r[2]), "=r"(r[3]) : "r"(addr));
}
__device__ __forceinline__ void ldmx2(uint32_t* r, uint32_t addr) {
    asm volatile("ldmatrix.sync.aligned.m8n8.x2.shared.b16 {%0,%1}, [%2];"
                 : "=r"(r[0]), "=r"(r[1]) : "r"(addr));
}
__device__ __forceinline__ void mma_bf16(float* d, const uint32_t* a,
                                         uint32_t b0, uint32_t b1) {
    asm volatile("mma.sync.aligned.m16n8k16.row.col.f32.bf16.bf16.f32 "
                 "{%0,%1,%2,%3}, {%4,%5,%6,%7}, {%8,%9}, {%0,%1,%2,%3};"
                 : "+f"(d[0]), "+f"(d[1]), "+f"(d[2]), "+f"(d[3])
                 : "r"(a[0]), "r"(a[1]), "r"(a[2]), "r"(a[3]), "r"(b0), "r"(b1));
}
__device__ __forceinline__ void cpa16(uint32_t saddr, const void* g) {
    asm volatile("cp.async.cg.shared.global [%0], [%1], 16;" :: "r"(saddr), "l"(g));
}
#define CPA_COMMIT() asm volatile("cp.async.commit_group;" ::: "memory")
#define CPA_WAIT(n)  asm volatile("cp.async.wait_group %0;" :: "n"(n) : "memory")

// ---------------- init ----------------
__global__ void init_state() {
    int idx = blockIdx.x * 256 + threadIdx.x;      // 32768 = exactly g_hb[0] in u32
    reinterpret_cast<uint32_t*>(g_hb)[idx] = 0u;
    if (idx < NBLK) g_arrive[idx] = 0u;
}

// ---------------- bf16 split conversions ----------------
__global__ void convert_x(const float* __restrict__ X) {
    size_t i = (size_t)blockIdx.x * 256 + threadIdx.x;
    size_t row = i >> 7;
    int    k4  = (int)(i & 127) << 2;
    int    s = (int)(row >> 6), b = (int)(row & 63);
    float4 v = *reinterpret_cast<const float4*>(X + ((size_t)b * S_ + s) * I_ + k4);
    union { __nv_bfloat16 h[4]; uint2 u; } Hh, Ll;
    float f[4] = {v.x, v.y, v.z, v.w};
#pragma unroll
    for (int j = 0; j < 4; ++j) {
        Hh.h[j] = __float2bfloat16_rn(f[j]);
        Ll.h[j] = __float2bfloat16_rn(f[j] - __bfloat162float(Hh.h[j]));
    }
    *reinterpret_cast<uint2*>(g_xhi + row * I_ + k4) = Hh.u;
    *reinterpret_cast<uint2*>(g_xlo + row * I_ + k4) = Ll.u;
}

__global__ void convert_w(const float* __restrict__ W) {
    int idx = blockIdx.x * 256 + threadIdx.x;
    int n = idx >> 9, k = idx & 511;
    float v = W[(size_t)k * NCOL + n];
    __nv_bfloat16 hi = __float2bfloat16_rn(v);
    g_wthi[idx] = hi;
    g_wtlo[idx] = __float2bfloat16_rn(v - __bfloat162float(hi));
}

// ---------------- precompute GEMM: mma.sync bf16, 3-term split ----------
// D[m'][n] = sum X W + bias. M=131072, N=2560, K=512 (x3 passes = 48 chunks of 32)
// block 128x128, warps 4(M)x2(N); SMEM rows padded to 80B for conflict-free ldmatrix
#define GSTRIDE 80
#define GOFF_A0 0
#define GOFF_A1 10240
#define GOFF_B0 20480
#define GOFF_B1 30720
#define GEMM_SMEM 40960

__global__ void __launch_bounds__(256, 2)
gemm_mma(const float* __restrict__ bias) {
    extern __shared__ char smem[];
    const uint32_t sb = smem_u32(smem);
    const int tid = threadIdx.x;
    const int wid = tid >> 5, lane = tid & 31;
    const int mw = wid & 3, nw = wid >> 1 & 0; // placeholder, fixed below
    const int mwarp = wid & 3;
    const int nwarp = wid >> 2;
    const int ntile = blockIdx.x * 128;
    const size_t mtile = (size_t)blockIdx.y * 128;

    (void)mw; (void)nw;

    float d[2][8][4];
#pragma unroll
    for (int t = 0; t < 2; ++t)
#pragma unroll
        for (int tt = 0; tt < 8; ++tt)
#pragma unroll
            for (int q = 0; q < 4; ++q) d[t][tt][q] = 0.f;

    const uint32_t offA[2] = {sb + GOFF_A0, sb + GOFF_A1};
    const uint32_t offB[2] = {sb + GOFF_B0, sb + GOFF_B1};

    // ldmatrix lane address components
    const int rA  = mwarp * 32 + (lane & 15);           // + t*16
    const int kbA = (lane & 16) ? 16 : 0;
    const int nB  = nwarp * 64 + ((lane >> 4) << 3) + (lane & 7);  // + pp*16
    const int kbB = (lane & 8) ? 16 : 0;

    // staging mapping: 2 x 16B per thread for each of A and B
    const int r0s = tid >> 2,          c0s = (tid & 3);
    const int r1s = (tid + 256) >> 2,  c1s = (tid & 3);

    auto issue = [&](int it, int buf) {
        const int seg = it >> 4;
        const int kk  = (it & 15) * 32;
        const __nv_bfloat16* Asrc = (seg == 1) ? g_xlo : g_xhi;
        const __nv_bfloat16* Bsrc = (seg == 2) ? g_wtlo : g_wthi;
        cpa16(offA[buf] + r0s * GSTRIDE + c0s * 16, Asrc + (mtile + r0s) * 512 + kk + c0s * 8);
        cpa16(offA[buf] + r1s * GSTRIDE + c1s * 16, Asrc + (mtile + r1s) * 512 + kk + c1s * 8);
        cpa16(offB[buf] + r0s * GSTRIDE + c0s * 16, Bsrc + (size_t)(ntile + r0s) * 512 + kk + c0s * 8);
        cpa16(offB[buf] + r1s * GSTRIDE + c1s * 16, Bsrc + (size_t)(ntile + r1s) * 512 + kk + c1s * 8);
        CPA_COMMIT();
    };

    issue(0, 0);
    for (int it = 0; it < 48; ++it) {
        const int buf = it & 1;
        if (it + 1 < 48) { issue(it + 1, buf ^ 1); CPA_WAIT(1); }
        else             { CPA_WAIT(0); }
        __syncthreads();

        const uint32_t ab = offA[buf], bb = offB[buf];
#pragma unroll
        for (int s = 0; s < 2; ++s) {
            uint32_t a[2][4];
            ldmx4(a[0], ab + (rA +  0) * GSTRIDE + s * 32 + kbA);
            ldmx4(a[1], ab + (rA + 16) * GSTRIDE + s * 32 + kbA);
            uint32_t bq[4][4];
#pragma unroll
            for (int pp = 0; pp < 4; ++pp)
                ldmx4(bq[pp], bb + (nB + pp * 16) * GSTRIDE + s * 32 + kbB);
#pragma unroll
            for (int t = 0; t < 2; ++t)
#pragma unroll
                for (int pp = 0; pp < 4; ++pp) {
                    mma_bf16(d[t][2 * pp],     a[t], bq[pp][0], bq[pp][1]);
                    mma_bf16(d[t][2 * pp + 1], a[t], bq[pp][2], bq[pp][3]);
                }
        }
        __syncthreads();
    }

    // epilogue: + bias, write fp32
#pragma unroll
    for (int t = 0; t < 2; ++t)
#pragma unroll
        for (int tt = 0; tt < 8; ++tt) {
            size_t row = mtile + mwarp * 32 + t * 16 + (lane >> 2);
            int    col = ntile + nwarp * 64 + tt * 8 + (lane & 3) * 2;
            float b0 = __ldg(bias + col), b1 = __ldg(bias + col + 1);
            float2 v0 = {d[t][tt][0] + b0, d[t][tt][1] + b1};
            float2 v1 = {d[t][tt][2] + b0, d[t][tt][3] + b1};
            *reinterpret_cast<float2*>(g_xz + row * NCOL + col)       = v0;
            *reinterpret_cast<float2*>(g_xz + (row + 8) * NCOL + col) = v1;
        }
}

// ---------------- recurrent kernel: HMMA bf16 split ----------------
// SMEM: W [24 rows][1024 k] bf16 (hi k0-511, lo k512-1023), stride 2048B, swizzled
//       h  hi[64][512] + lo[64][512] bf16, stride 1024B, swizzled
//       zbuf [64][24] fp32
#define ROFF_W 0
#define ROFF_H 49152
#define ROFF_Z 180224
#define RSMEM  186368

__device__ __forceinline__ float sigmoidf_(float x) {
    return 1.f / (1.f + __expf(-x));
}

__global__ void __launch_bounds__(256, 1)
lstm_recurrent(const float* __restrict__ W, float* __restrict__ y) {
    extern __shared__ char smem[];
    const uint32_t sb = smem_u32(smem);
    const int tid  = threadIdx.x;
    const int wid  = tid >> 5, lane = tid & 31;
    const int mw   = wid & 3;        // M-tile (rows mw*16..+15)
    const int kw   = wid >> 2;       // K-half (kw*256 per pass)
    const int bid  = blockIdx.x;
    const int j0   = bid * 4;

    // ---- zero W region (incl. pad rows 20-23), then fill 20 rows hi/lo ----
    for (int i = tid; i < 49152 / 16; i += 256) {
        uint4 z = {0, 0, 0, 0};
        *reinterpret_cast<uint4*>(smem + ROFF_W + i * 16) = z;
    }
    __syncthreads();
    for (int idx = tid; idx < 20 * 512; idx += 256) {
        int c = idx >> 9, k = idx & 511;
        int g = c >> 2, jj = c & 3;
        float v = W[(size_t)(I_ + k) * NCOL + g * H_ + j0 + jj];
        __nv_bfloat16 hi = __float2bfloat16_rn(v);
        __nv_bfloat16 lo = __float2bfloat16_rn(v - __bfloat162float(hi));
        uint32_t X = (uint32_t)(c & 7) << 4;
        *reinterpret_cast<__nv_bfloat16*>(smem + ROFF_W + c * 2048 + ((k * 2) ^ X)) = hi;
        *reinterpret_cast<__nv_bfloat16*>(smem + ROFF_W + c * 2048 + (((1024 + k * 2)) ^ X)) = lo;
    }

    // gate identity: one (b, j) per thread, c-state in register
    const int b_r  = tid >> 2;
    const int jj_r = tid & 3;
    const int j_r  = j0 + jj_r;
    float c_state = 0.f;

    // ldmatrix lane components
    const int rAr  = mw * 16 + (lane & 15);
    const int kbA  = (lane & 16) ? 16 : 0;
    const uint32_t XA = (uint32_t)(rAr & 7) << 4;
    const uint32_t aRow = sb + ROFF_H + (uint32_t)rAr * 1024;

    const int nB4  = ((lane >> 4) << 3) + (lane & 7);     // n-tiles 0,1
    const int kbB4 = (lane & 8) ? 16 : 0;
    const uint32_t XB4 = (uint32_t)(nB4 & 7) << 4;
    const uint32_t b4Row = sb + ROFF_W + (uint32_t)nB4 * 2048;

    const int nB2  = 16 + (lane & 7);                     // n-tile 2
    const int kbB2 = (lane & 8) ? 16 : 0;
    const uint32_t XB2 = (uint32_t)(nB2 & 7) << 4;
    const uint32_t b2Row = sb + ROFF_W + (uint32_t)nB2 * 2048;

    float* zb = reinterpret_cast<float*>(smem + ROFF_Z);
    const int rrow = mw * 16 + (lane >> 2);
    const int rcol = (lane & 3) * 2;

    __syncthreads();

    for (int s = 0; s < S_; ++s) {
        const int pp = s & 1;

        // prefetch xz gate pre-activations
        float xzv[5];
        {
            const float* xp = g_xz + ((size_t)s * B_ + b_r) * NCOL + j_r;
#pragma unroll
            for (int g = 0; g < 5; ++g) xzv[g] = __ldg(xp + g * H_);
        }

        // stage h (bf16 hi+lo, 128KB) into swizzled SMEM
        {
            const uint4* hsrc = reinterpret_cast<const uint4*>(&g_hb[pp][0][0]);
            for (int q = tid; q < 8192; q += 256) {
                uint4 v = __ldcg(hsrc + q);
                int half = q >> 12, rem = q & 4095;
                int b = rem >> 6, k8 = rem & 63;
                uint32_t off = (uint32_t)half * 65536 + (uint32_t)b * 1024 +
                               (((uint32_t)k8 * 16) ^ ((uint32_t)(b & 7) << 4));
                *reinterpret_cast<uint4*>(smem + ROFF_H + off) = v;
            }
        }
        __syncthreads();

        // 3-pass HMMA: (h_hi,W_hi), (h_lo,W_hi), (h_hi,W_lo)
        float acc[3][4];
#pragma unroll
        for (int t = 0; t < 3; ++t)
#pragma unroll
            for (int q = 0; q < 4; ++q) acc[t][q] = 0.f;

        const uint32_t halfOff[3] = {0, 65536, 0};
        const uint32_t wcolOff[3] = {0, 0, 1024};
#pragma unroll
        for (int pass = 0; pass < 3; ++pass) {
            const uint32_t aBase = aRow + halfOff[pass];
            const uint32_t wOff  = wcolOff[pass] + (uint32_t)kw * 512;
#pragma unroll 4
            for (int st = 0; st < 16; ++st) {
                uint32_t kb = (uint32_t)kw * 512 + (uint32_t)st * 32;
                uint32_t a[4], b01[4], b2[2];
                ldmx4(a,   aBase + ((kb + kbA) ^ XA));
                ldmx4(b01, b4Row + ((wcolOff[pass] + kb + kbB4) ^ XB4));
                ldmx2(b2,  b2Row + ((wcolOff[pass] + kb + kbB2) ^ XB2));
                mma_bf16(acc[0], a, b01[0], b01[1]);
                mma_bf16(acc[1], a, b01[2], b01[3]);
                mma_bf16(acc[2], a, b2[0], b2[1]);
            }
            (void)wOff;
        }

        // K-reduction across kw pairs via SMEM
        if (kw == 1) {
#pragma unroll
            for (int t = 0; t < 3; ++t) {
                zb[rrow * 24 + t * 8 + rcol]           = acc[t][0];
                zb[rrow * 24 + t * 8 + rcol + 1]       = acc[t][1];
                zb[(rrow + 8) * 24 + t * 8 + rcol]     = acc[t][2];
                zb[(rrow + 8) * 24 + t * 8 + rcol + 1] = acc[t][3];
            }
        }
        __syncthreads();
        if (kw == 0) {
#pragma unroll
            for (int t = 0; t < 3; ++t) {
                zb[rrow * 24 + t * 8 + rcol]           += acc[t][0];
                zb[rrow * 24 + t * 8 + rcol + 1]       += acc[t][1];
                zb[(rrow + 8) * 24 + t * 8 + rcol]     += acc[t][2];
                zb[(rrow + 8) * 24 + t * 8 + rcol + 1] += acc[t][3];
            }
        }
        __syncthreads();

        // gates
        float z[5];
#pragma unroll
        for (int g = 0; g < 5; ++g) z[g] = zb[b_r * 24 + g * 4 + jj_r] + xzv[g];
        float it = sigmoidf_(z[0]);
        float ft = sigmoidf_(z[1]);
        float ot = sigmoidf_(z[2]);
        float tc = tanhf(z[3]);
        float dt = tanhf(z[4]);
        float cp = ft * c_state + it * tc;
        float cn = cp + dt * (cp - c_state);   // highway update
        c_state = cn;
        float hn = ot * tanhf(cn);

        y[((size_t)b_r * S_ + s) * H_ + j_r] = hn;
        {
            __nv_bfloat16 hi = __float2bfloat16_rn(hn);
            __nv_bfloat16 lo = __float2bfloat16_rn(hn - __bfloat162float(hi));
            g_hb[pp ^ 1][0][b_r * H_ + j_r] = hi;
            g_hb[pp ^ 1][1][b_r * H_ + j_r] = lo;
        }

        // grid barrier
        __threadfence();
        __syncthreads();
        if (tid == 0)
            *reinterpret_cast<volatile unsigned*>(&g_arrive[bid]) = (unsigned)(s + 1);
        if (tid < NBLK) {
            while (*reinterpret_cast<volatile unsigned*>(&g_arrive[tid]) < (unsigned)(s + 1)) {
                __nanosleep(32);
            }
        }
        __threadfence();
        __syncthreads();
    }
}

// ---------------- launch ----------------
extern "C" void kernel_launch(void* const* d_in, const int* in_sizes, int n_in,
                              void* d_out, int out_size) {
    const float* x    = (const float*)d_in[0];  // [B,S,I]
    const float* W    = (const float*)d_in[1];  // [I+H, 5H]
    const float* bias = (const float*)d_in[2];  // [5H]
    float* y = (float*)d_out;                   // [B,S,H]

    cudaFuncSetAttribute(lstm_recurrent,
                         cudaFuncAttributeMaxDynamicSharedMemorySize, RSMEM);
    cudaFuncSetAttribute(gemm_mma,
                         cudaFuncAttributeMaxDynamicSharedMemorySize, GEMM_SMEM);

    init_state<<<128, 256>>>();
    convert_x<<<65536, 256>>>(x);
    convert_w<<<5120, 256>>>(W);

    dim3 grid(NCOL / 128, (B_ * (size_t)S_) / 128);   // (20, 1024)
    gemm_mma<<<grid, 256, GEMM_SMEM>>>(bias);

    lstm_recurrent<<<NBLK, 256, RSMEM>>>(W, y);
}

// round 4
// speedup vs baseline: 1.6317x; 1.2476x over previous
#include <cuda_runtime.h>
#include <cuda_bf16.h>
#include <cstdint>
#include <cstddef>

#define B_    64
#define S_    2048
#define I_    512
#define H_    512
#define NCOL  2560   // 5*H
#define NBLK  128    // persistent blocks for recurrence

// ---------------- device scratch (no allocations allowed) ----------------
__device__ float          g_xz[335544320];       // [S*B][5H] fp32
__device__ __nv_bfloat16  g_hb[2][2][B_ * H_];   // [pingpong][hi/lo][b*512+j]
__device__ unsigned       g_arrive[NBLK];        // grid-barrier flags
__device__ __nv_bfloat16  g_xhi[67108864];       // [S*B][512] bf16 hi
__device__ __nv_bfloat16  g_xlo[67108864];       // [S*B][512] bf16 lo
__device__ __nv_bfloat16  g_wthi[NCOL * 512];    // W[0:512][:] transposed [n][k]
__device__ __nv_bfloat16  g_wtlo[NCOL * 512];

// ---------------- PTX helpers (baseline PTX only, no sm_103a features) ----
__device__ __forceinline__ uint32_t smem_u32(const void* p) {
    uint32_t a;
    asm("{ .reg .u64 t; cvta.to.shared.u64 t, %1; cvt.u32.u64 %0, t; }" : "=r"(a) : "l"(p));
    return a;
}
__device__ __forceinline__ void ldmx4(uint32_t* r, uint32_t addr) {
    asm volatile("ldmatrix.sync.aligned.m8n8.x4.shared.b16 {%0,%1,%2,%3}, [%4];"
                 : "=r"(r[0]), "=r"(r[1]), "=r"(r[2]), "=r"(r[3]) : "r"(addr));
}
__device__ __forceinline__ void ldmx2(uint32_t* r, uint32_t addr) {
    asm volatile("ldmatrix.sync.aligned.m8n8.x2.shared.b16 {%0,%1}, [%2];"
                 : "=r"(r[0]), "=r"(r[1]) : "r"(addr));
}
__device__ __forceinline__ void mma_bf16(float* d, const uint32_t* a,
                                         uint32_t b0, uint32_t b1) {
    asm volatile("mma.sync.aligned.m16n8k16.row.col.f32.bf16.bf16.f32 "
                 "{%0,%1,%2,%3}, {%4,%5,%6,%7}, {%8,%9}, {%0,%1,%2,%3};"
                 : "+f"(d[0]), "+f"(d[1]), "+f"(d[2]), "+f"(d[3])
                 : "r"(a[0]), "r"(a[1]), "r"(a[2]), "r"(a[3]), "r"(b0), "r"(b1));
}
__device__ __forceinline__ void cpa16(uint32_t saddr, const void* g) {
    asm volatile("cp.async.cg.shared.global [%0], [%1], 16;" :: "r"(saddr), "l"(g));
}
#define CPA_COMMIT() asm volatile("cp.async.commit_group;" ::: "memory")
#define CPA_WAIT(n)  asm volatile("cp.async.wait_group %0;" :: "n"(n) : "memory")

__device__ __forceinline__ unsigned ld_acq(const unsigned* p) {
    unsigned v;
    asm volatile("ld.acquire.gpu.global.u32 %0, [%1];" : "=r"(v) : "l"(p) : "memory");
    return v;
}
__device__ __forceinline__ void st_rel(unsigned* p, unsigned v) {
    asm volatile("st.release.gpu.global.u32 [%0], %1;" :: "l"(p), "r"(v) : "memory");
}

// ---------------- init ----------------
__global__ void init_state() {
    int idx = blockIdx.x * 256 + threadIdx.x;      // 32768 = exactly g_hb[0] in u32
    reinterpret_cast<uint32_t*>(g_hb)[idx] = 0u;
    if (idx < NBLK) g_arrive[idx] = 0u;
}

// ---------------- bf16 split conversions ----------------
__global__ void convert_x(const float* __restrict__ X) {
    size_t i = (size_t)blockIdx.x * 256 + threadIdx.x;
    size_t row = i >> 7;
    int    k4  = (int)(i & 127) << 2;
    int    s = (int)(row >> 6), b = (int)(row & 63);
    float4 v = *reinterpret_cast<const float4*>(X + ((size_t)b * S_ + s) * I_ + k4);
    union { __nv_bfloat16 h[4]; uint2 u; } Hh, Ll;
    float f[4] = {v.x, v.y, v.z, v.w};
#pragma unroll
    for (int j = 0; j < 4; ++j) {
        Hh.h[j] = __float2bfloat16_rn(f[j]);
        Ll.h[j] = __float2bfloat16_rn(f[j] - __bfloat162float(Hh.h[j]));
    }
    *reinterpret_cast<uint2*>(g_xhi + row * I_ + k4) = Hh.u;
    *reinterpret_cast<uint2*>(g_xlo + row * I_ + k4) = Ll.u;
}

__global__ void convert_w(const float* __restrict__ W) {
    int idx = blockIdx.x * 256 + threadIdx.x;
    int n = idx >> 9, k = idx & 511;
    float v = W[(size_t)k * NCOL + n];
    __nv_bfloat16 hi = __float2bfloat16_rn(v);
    g_wthi[idx] = hi;
    g_wtlo[idx] = __float2bfloat16_rn(v - __bfloat162float(hi));
}

// ---------------- precompute GEMM: mma.sync bf16, 3-term split ----------
#define GSTRIDE 80
#define GOFF_A0 0
#define GOFF_A1 10240
#define GOFF_B0 20480
#define GOFF_B1 30720
#define GEMM_SMEM 40960

__global__ void __launch_bounds__(256, 2)
gemm_mma(const float* __restrict__ bias) {
    extern __shared__ char smem[];
    const uint32_t sb = smem_u32(smem);
    const int tid = threadIdx.x;
    const int wid = tid >> 5, lane = tid & 31;
    const int mwarp = wid & 3;
    const int nwarp = wid >> 2;
    const int ntile = blockIdx.x * 128;
    const size_t mtile = (size_t)blockIdx.y * 128;

    float d[2][8][4];
#pragma unroll
    for (int t = 0; t < 2; ++t)
#pragma unroll
        for (int tt = 0; tt < 8; ++tt)
#pragma unroll
            for (int q = 0; q < 4; ++q) d[t][tt][q] = 0.f;

    const uint32_t offA[2] = {sb + GOFF_A0, sb + GOFF_A1};
    const uint32_t offB[2] = {sb + GOFF_B0, sb + GOFF_B1};

    const int rA  = mwarp * 32 + (lane & 15);
    const int kbA = (lane & 16) ? 16 : 0;
    const int nB  = nwarp * 64 + ((lane >> 4) << 3) + (lane & 7);
    const int kbB = (lane & 8) ? 16 : 0;

    const int r0s = tid >> 2,          c0s = (tid & 3);
    const int r1s = (tid + 256) >> 2,  c1s = (tid & 3);

    auto issue = [&](int it, int buf) {
        const int seg = it >> 4;
        const int kk  = (it & 15) * 32;
        const __nv_bfloat16* Asrc = (seg == 1) ? g_xlo : g_xhi;
        const __nv_bfloat16* Bsrc = (seg == 2) ? g_wtlo : g_wthi;
        cpa16(offA[buf] + r0s * GSTRIDE + c0s * 16, Asrc + (mtile + r0s) * 512 + kk + c0s * 8);
        cpa16(offA[buf] + r1s * GSTRIDE + c1s * 16, Asrc + (mtile + r1s) * 512 + kk + c1s * 8);
        cpa16(offB[buf] + r0s * GSTRIDE + c0s * 16, Bsrc + (size_t)(ntile + r0s) * 512 + kk + c0s * 8);
        cpa16(offB[buf] + r1s * GSTRIDE + c1s * 16, Bsrc + (size_t)(ntile + r1s) * 512 + kk + c1s * 8);
        CPA_COMMIT();
    };

    issue(0, 0);
    for (int it = 0; it < 48; ++it) {
        const int buf = it & 1;
        if (it + 1 < 48) { issue(it + 1, buf ^ 1); CPA_WAIT(1); }
        else             { CPA_WAIT(0); }
        __syncthreads();

        const uint32_t ab = offA[buf], bb = offB[buf];
#pragma unroll
        for (int s = 0; s < 2; ++s) {
            uint32_t a[2][4];
            ldmx4(a[0], ab + (rA +  0) * GSTRIDE + s * 32 + kbA);
            ldmx4(a[1], ab + (rA + 16) * GSTRIDE + s * 32 + kbA);
            uint32_t bq[4][4];
#pragma unroll
            for (int pp = 0; pp < 4; ++pp)
                ldmx4(bq[pp], bb + (nB + pp * 16) * GSTRIDE + s * 32 + kbB);
#pragma unroll
            for (int t = 0; t < 2; ++t)
#pragma unroll
                for (int pp = 0; pp < 4; ++pp) {
                    mma_bf16(d[t][2 * pp],     a[t], bq[pp][0], bq[pp][1]);
                    mma_bf16(d[t][2 * pp + 1], a[t], bq[pp][2], bq[pp][3]);
                }
        }
        __syncthreads();
    }

#pragma unroll
    for (int t = 0; t < 2; ++t)
#pragma unroll
        for (int tt = 0; tt < 8; ++tt) {
            size_t row = mtile + mwarp * 32 + t * 16 + (lane >> 2);
            int    col = ntile + nwarp * 64 + tt * 8 + (lane & 3) * 2;
            float b0 = __ldg(bias + col), b1 = __ldg(bias + col + 1);
            float2 v0 = {d[t][tt][0] + b0, d[t][tt][1] + b1};
            float2 v1 = {d[t][tt][2] + b0, d[t][tt][3] + b1};
            *reinterpret_cast<float2*>(g_xz + row * NCOL + col)       = v0;
            *reinterpret_cast<float2*>(g_xz + (row + 8) * NCOL + col) = v1;
        }
}

// ---------------- recurrent kernel: HMMA bf16 split ----------------
#define ROFF_W 0
#define ROFF_H 49152
#define ROFF_Z 180224
#define RSMEM  186368

__device__ __forceinline__ float fast_sigmoid(float x) {
    return 1.f / (1.f + __expf(-x));
}
__device__ __forceinline__ float fast_tanh(float x) {
    float ax = fabsf(x);
    float e  = __expf(-2.f * ax);
    float t  = (1.f - e) / (1.f + e);
    return copysignf(t, x);
}

__global__ void __launch_bounds__(256, 1)
lstm_recurrent(const float* __restrict__ W, float* __restrict__ y) {
    extern __shared__ char smem[];
    const uint32_t sb = smem_u32(smem);
    const int tid  = threadIdx.x;
    const int wid  = tid >> 5, lane = tid & 31;
    const int mw   = wid & 3;        // M-tile (rows mw*16..+15)
    const int kw   = wid >> 2;       // K-half
    const int bid  = blockIdx.x;
    const int j0   = bid * 4;

    // zero W region (incl. pad rows 20-23), then fill 20 rows hi/lo
    for (int i = tid; i < 49152 / 16; i += 256) {
        uint4 z = {0, 0, 0, 0};
        *reinterpret_cast<uint4*>(smem + ROFF_W + i * 16) = z;
    }
    __syncthreads();
    for (int idx = tid; idx < 20 * 512; idx += 256) {
        int c = idx >> 9, k = idx & 511;
        int g = c >> 2, jj = c & 3;
        float v = W[(size_t)(I_ + k) * NCOL + g * H_ + j0 + jj];
        __nv_bfloat16 hi = __float2bfloat16_rn(v);
        __nv_bfloat16 lo = __float2bfloat16_rn(v - __bfloat162float(hi));
        uint32_t X = (uint32_t)(c & 7) << 4;
        *reinterpret_cast<__nv_bfloat16*>(smem + ROFF_W + c * 2048 + ((k * 2) ^ X)) = hi;
        *reinterpret_cast<__nv_bfloat16*>(smem + ROFF_W + c * 2048 + ((1024 + k * 2) ^ X)) = lo;
    }

    // gate identity: one (b, j) per thread, c-state in register
    const int b_r  = tid >> 2;
    const int jj_r = tid & 3;
    const int j_r  = j0 + jj_r;
    float c_state = 0.f;

    // ldmatrix lane components
    const int rAr  = mw * 16 + (lane & 15);
    const int kbA  = (lane & 16) ? 16 : 0;
    const uint32_t XA = (uint32_t)(rAr & 7) << 4;
    const uint32_t aRow = sb + ROFF_H + (uint32_t)rAr * 1024;

    const int nB4  = ((lane >> 4) << 3) + (lane & 7);
    const int kbB4 = (lane & 8) ? 16 : 0;
    const uint32_t XB4 = (uint32_t)(nB4 & 7) << 4;
    const uint32_t b4Row = sb + ROFF_W + (uint32_t)nB4 * 2048;

    const int nB2  = 16 + (lane & 7);
    const int kbB2 = (lane & 8) ? 16 : 0;
    const uint32_t XB2 = (uint32_t)(nB2 & 7) << 4;
    const uint32_t b2Row = sb + ROFF_W + (uint32_t)nB2 * 2048;

    float* zb = reinterpret_cast<float*>(smem + ROFF_Z);
    const int rrow = mw * 16 + (lane >> 2);
    const int rcol = (lane & 3) * 2;

    // precompute cp.async staging addresses (32 iters of q = tid + 256*i)
    __syncthreads();

    for (int s = 0; s < S_; ++s) {
        const int pp = s & 1;

        // prefetch xz gate pre-activations (in-flight during staging)
        float xzv[5];
        {
            const float* xp = g_xz + ((size_t)s * B_ + b_r) * NCOL + j_r;
#pragma unroll
            for (int g = 0; g < 5; ++g) xzv[g] = __ldg(xp + g * H_);
        }

        // stage h (bf16 hi+lo, 128KB) into swizzled SMEM via cp.async
        {
            const uint4* hsrc = reinterpret_cast<const uint4*>(&g_hb[pp][0][0]);
#pragma unroll 8
            for (int q = tid; q < 8192; q += 256) {
                int half = q >> 12, rem = q & 4095;
                int b = rem >> 6, k8 = rem & 63;
                uint32_t off = (uint32_t)half * 65536 + (uint32_t)b * 1024 +
                               (((uint32_t)k8 * 16) ^ ((uint32_t)(b & 7) << 4));
                cpa16(sb + ROFF_H + off, hsrc + q);
            }
            CPA_COMMIT();
            CPA_WAIT(0);
        }
        __syncthreads();

        // 3-pass HMMA: (h_hi,W_hi), (h_lo,W_hi), (h_hi,W_lo)
        float acc[3][4];
#pragma unroll
        for (int t = 0; t < 3; ++t)
#pragma unroll
            for (int q = 0; q < 4; ++q) acc[t][q] = 0.f;

        const uint32_t halfOff[3] = {0, 65536, 0};
        const uint32_t wcolOff[3] = {0, 0, 1024};
#pragma unroll
        for (int pass = 0; pass < 3; ++pass) {
            const uint32_t aBase = aRow + halfOff[pass];
#pragma unroll 4
            for (int st = 0; st < 16; ++st) {
                uint32_t kb = (uint32_t)kw * 512 + (uint32_t)st * 32;
                uint32_t a[4], b01[4], b2[2];
                ldmx4(a,   aBase + ((kb + kbA) ^ XA));
                ldmx4(b01, b4Row + ((wcolOff[pass] + kb + kbB4) ^ XB4));
                ldmx2(b2,  b2Row + ((wcolOff[pass] + kb + kbB2) ^ XB2));
                mma_bf16(acc[0], a, b01[0], b01[1]);
                mma_bf16(acc[1], a, b01[2], b01[3]);
                mma_bf16(acc[2], a, b2[0], b2[1]);
            }
        }

        // K-reduction across kw pairs via SMEM
        if (kw == 1) {
#pragma unroll
            for (int t = 0; t < 3; ++t) {
                zb[rrow * 24 + t * 8 + rcol]           = acc[t][0];
                zb[rrow * 24 + t * 8 + rcol + 1]       = acc[t][1];
                zb[(rrow + 8) * 24 + t * 8 + rcol]     = acc[t][2];
                zb[(rrow + 8) * 24 + t * 8 + rcol + 1] = acc[t][3];
            }
        }
        __syncthreads();
        if (kw == 0) {
#pragma unroll
            for (int t = 0; t < 3; ++t) {
                zb[rrow * 24 + t * 8 + rcol]           += acc[t][0];
                zb[rrow * 24 + t * 8 + rcol + 1]       += acc[t][1];
                zb[(rrow + 8) * 24 + t * 8 + rcol]     += acc[t][2];
                zb[(rrow + 8) * 24 + t * 8 + rcol + 1] += acc[t][3];
            }
        }
        __syncthreads();

        // gates
        float z[5];
#pragma unroll
        for (int g = 0; g < 5; ++g) z[g] = zb[b_r * 24 + g * 4 + jj_r] + xzv[g];
        float it = fast_sigmoid(z[0]);
        float ft = fast_sigmoid(z[1]);
        float ot = fast_sigmoid(z[2]);
        float tc = fast_tanh(z[3]);
        float dt = fast_tanh(z[4]);
        float cp = ft * c_state + it * tc;
        float cn = cp + dt * (cp - c_state);   // highway update
        c_state = cn;
        float hn = ot * fast_tanh(cn);

        // h store FIRST (critical path), publish, then y store off-path
        {
            __nv_bfloat16 hi = __float2bfloat16_rn(hn);
            __nv_bfloat16 lo = __float2bfloat16_rn(hn - __bfloat162float(hi));
            g_hb[pp ^ 1][0][b_r * H_ + j_r] = hi;
            g_hb[pp ^ 1][1][b_r * H_ + j_r] = lo;
        }
        __syncthreads();                     // all h stores done CTA-wide
        if (tid == 0) st_rel(&g_arrive[bid], (unsigned)(s + 1));

        y[((size_t)b_r * S_ + s) * H_ + j_r] = hn;

        // pure-spin acquire barrier (no nanosleep, no threadfence)
        if (tid < NBLK) {
            const unsigned tgt = (unsigned)(s + 1);
            while (ld_acq(&g_arrive[tid]) < tgt) { }
        }
        __syncthreads();
    }
}

// ---------------- launch ----------------
extern "C" void kernel_launch(void* const* d_in, const int* in_sizes, int n_in,
                              void* d_out, int out_size) {
    const float* x    = (const float*)d_in[0];  // [B,S,I]
    const float* W    = (const float*)d_in[1];  // [I+H, 5H]
    const float* bias = (const float*)d_in[2];  // [5H]
    float* y = (float*)d_out;                   // [B,S,H]

    cudaFuncSetAttribute(lstm_recurrent,
                         cudaFuncAttributeMaxDynamicSharedMemorySize, RSMEM);
    cudaFuncSetAttribute(gemm_mma,
                         cudaFuncAttributeMaxDynamicSharedMemorySize, GEMM_SMEM);

    init_state<<<128, 256>>>();
    convert_x<<<65536, 256>>>(x);
    convert_w<<<5120, 256>>>(W);

    dim3 grid(NCOL / 128, (B_ * (size_t)S_) / 128);   // (20, 1024)
    gemm_mma<<<grid, 256, GEMM_SMEM>>>(bias);

    lstm_recurrent<<<NBLK, 256, RSMEM>>>(W, y);
}

// round 5
// speedup vs baseline: 1.6632x; 1.0193x over previous
#include <cuda_runtime.h>
#include <cuda_bf16.h>
#include <cstdint>
#include <cstddef>

#define B_    64
#define S_    2048
#define I_    512
#define H_    512
#define NCOL  2560   // 5*H
#define NBLK  128    // persistent blocks for recurrence

// ---------------- device scratch (no allocations allowed) ----------------
__device__ float          g_xz[335544320];       // [S*B][5H] fp32
__device__ __nv_bfloat16  g_hb[2][2][B_ * H_];   // [pingpong][hi/lo][b*512+j]
__device__ unsigned       g_arrive[NBLK];        // grid-barrier flags
__device__ __nv_bfloat16  g_xhi[67108864];       // [S*B][512] bf16 hi
__device__ __nv_bfloat16  g_xlo[67108864];       // [S*B][512] bf16 lo
__device__ __nv_bfloat16  g_wthi[NCOL * 512];    // W[0:512][:] transposed [n][k]
__device__ __nv_bfloat16  g_wtlo[NCOL * 512];

// ---------------- PTX helpers (baseline PTX only, no sm_103a features) ----
__device__ __forceinline__ uint32_t smem_u32(const void* p) {
    uint32_t a;
    asm("{ .reg .u64 t; cvta.to.shared.u64 t, %1; cvt.u32.u64 %0, t; }" : "=r"(a) : "l"(p));
    return a;
}
__device__ __forceinline__ void ldmx4(uint32_t* r, uint32_t addr) {
    asm volatile("ldmatrix.sync.aligned.m8n8.x4.shared.b16 {%0,%1,%2,%3}, [%4];"
                 : "=r"(r[0]), "=r"(r[1]), "=r"(r[2]), "=r"(r[3]) : "r"(addr));
}
__device__ __forceinline__ void ldmx2(uint32_t* r, uint32_t addr) {
    asm volatile("ldmatrix.sync.aligned.m8n8.x2.shared.b16 {%0,%1}, [%2];"
                 : "=r"(r[0]), "=r"(r[1]) : "r"(addr));
}
__device__ __forceinline__ void mma_bf16(float* d, const uint32_t* a,
                                         uint32_t b0, uint32_t b1) {
    asm volatile("mma.sync.aligned.m16n8k16.row.col.f32.bf16.bf16.f32 "
                 "{%0,%1,%2,%3}, {%4,%5,%6,%7}, {%8,%9}, {%0,%1,%2,%3};"
                 : "+f"(d[0]), "+f"(d[1]), "+f"(d[2]), "+f"(d[3])
                 : "r"(a[0]), "r"(a[1]), "r"(a[2]), "r"(a[3]), "r"(b0), "r"(b1));
}
__device__ __forceinline__ void cpa16(uint32_t saddr, const void* g) {
    asm volatile("cp.async.cg.shared.global [%0], [%1], 16;" :: "r"(saddr), "l"(g));
}
#define CPA_COMMIT() asm volatile("cp.async.commit_group;" ::: "memory")
#define CPA_WAIT(n)  asm volatile("cp.async.wait_group %0;" :: "n"(n) : "memory")

__device__ __forceinline__ unsigned ld_acq(const unsigned* p) {
    unsigned v;
    asm volatile("ld.acquire.gpu.global.u32 %0, [%1];" : "=r"(v) : "l"(p) : "memory");
    return v;
}
__device__ __forceinline__ void st_rel(unsigned* p, unsigned v) {
    asm volatile("st.release.gpu.global.u32 [%0], %1;" :: "l"(p), "r"(v) : "memory");
}

// ---------------- bf16 split conversions (+ state init merged in) --------
__global__ void convert_x(const float* __restrict__ X) {
    // merged init: first 128 blocks also zero h0 ping-pong + barrier flags
    if (blockIdx.x < 128) {
        int idx = blockIdx.x * 256 + threadIdx.x;   // 32768 = all of g_hb in u32
        reinterpret_cast<uint32_t*>(g_hb)[idx] = 0u;
        if (idx < NBLK) g_arrive[idx] = 0u;
    }
    size_t i = (size_t)blockIdx.x * 256 + threadIdx.x;
    size_t row = i >> 7;
    int    k4  = (int)(i & 127) << 2;
    int    s = (int)(row >> 6), b = (int)(row & 63);
    float4 v = *reinterpret_cast<const float4*>(X + ((size_t)b * S_ + s) * I_ + k4);
    union { __nv_bfloat16 h[4]; uint2 u; } Hh, Ll;
    float f[4] = {v.x, v.y, v.z, v.w};
#pragma unroll
    for (int j = 0; j < 4; ++j) {
        Hh.h[j] = __float2bfloat16_rn(f[j]);
        Ll.h[j] = __float2bfloat16_rn(f[j] - __bfloat162float(Hh.h[j]));
    }
    *reinterpret_cast<uint2*>(g_xhi + row * I_ + k4) = Hh.u;
    *reinterpret_cast<uint2*>(g_xlo + row * I_ + k4) = Ll.u;
}

__global__ void convert_w(const float* __restrict__ W) {
    int idx = blockIdx.x * 256 + threadIdx.x;
    int n = idx >> 9, k = idx & 511;
    float v = W[(size_t)k * NCOL + n];
    __nv_bfloat16 hi = __float2bfloat16_rn(v);
    g_wthi[idx] = hi;
    g_wtlo[idx] = __float2bfloat16_rn(v - __bfloat162float(hi));
}

// ---------------- precompute GEMM: mma.sync bf16, 3-term split (frozen) --
#define GSTRIDE 80
#define GOFF_A0 0
#define GOFF_A1 10240
#define GOFF_B0 20480
#define GOFF_B1 30720
#define GEMM_SMEM 40960

__global__ void __launch_bounds__(256, 2)
gemm_mma(const float* __restrict__ bias) {
    extern __shared__ char smem[];
    const uint32_t sb = smem_u32(smem);
    const int tid = threadIdx.x;
    const int wid = tid >> 5, lane = tid & 31;
    const int mwarp = wid & 3;
    const int nwarp = wid >> 2;
    const int ntile = blockIdx.x * 128;
    const size_t mtile = (size_t)blockIdx.y * 128;

    float d[2][8][4];
#pragma unroll
    for (int t = 0; t < 2; ++t)
#pragma unroll
        for (int tt = 0; tt < 8; ++tt)
#pragma unroll
            for (int q = 0; q < 4; ++q) d[t][tt][q] = 0.f;

    const uint32_t offA[2] = {sb + GOFF_A0, sb + GOFF_A1};
    const uint32_t offB[2] = {sb + GOFF_B0, sb + GOFF_B1};

    const int rA  = mwarp * 32 + (lane & 15);
    const int kbA = (lane & 16) ? 16 : 0;
    const int nB  = nwarp * 64 + ((lane >> 4) << 3) + (lane & 7);
    const int kbB = (lane & 8) ? 16 : 0;

    const int r0s = tid >> 2,          c0s = (tid & 3);
    const int r1s = (tid + 256) >> 2,  c1s = (tid & 3);

    auto issue = [&](int it, int buf) {
        const int seg = it >> 4;
        const int kk  = (it & 15) * 32;
        const __nv_bfloat16* Asrc = (seg == 1) ? g_xlo : g_xhi;
        const __nv_bfloat16* Bsrc = (seg == 2) ? g_wtlo : g_wthi;
        cpa16(offA[buf] + r0s * GSTRIDE + c0s * 16, Asrc + (mtile + r0s) * 512 + kk + c0s * 8);
        cpa16(offA[buf] + r1s * GSTRIDE + c1s * 16, Asrc + (mtile + r1s) * 512 + kk + c1s * 8);
        cpa16(offB[buf] + r0s * GSTRIDE + c0s * 16, Bsrc + (size_t)(ntile + r0s) * 512 + kk + c0s * 8);
        cpa16(offB[buf] + r1s * GSTRIDE + c1s * 16, Bsrc + (size_t)(ntile + r1s) * 512 + kk + c1s * 8);
        CPA_COMMIT();
    };

    issue(0, 0);
    for (int it = 0; it < 48; ++it) {
        const int buf = it & 1;
        if (it + 1 < 48) { issue(it + 1, buf ^ 1); CPA_WAIT(1); }
        else             { CPA_WAIT(0); }
        __syncthreads();

        const uint32_t ab = offA[buf], bb = offB[buf];
#pragma unroll
        for (int s = 0; s < 2; ++s) {
            uint32_t a[2][4];
            ldmx4(a[0], ab + (rA +  0) * GSTRIDE + s * 32 + kbA);
            ldmx4(a[1], ab + (rA + 16) * GSTRIDE + s * 32 + kbA);
            uint32_t bq[4][4];
#pragma unroll
            for (int pp = 0; pp < 4; ++pp)
                ldmx4(bq[pp], bb + (nB + pp * 16) * GSTRIDE + s * 32 + kbB);
#pragma unroll
            for (int t = 0; t < 2; ++t)
#pragma unroll
                for (int pp = 0; pp < 4; ++pp) {
                    mma_bf16(d[t][2 * pp],     a[t], bq[pp][0], bq[pp][1]);
                    mma_bf16(d[t][2 * pp + 1], a[t], bq[pp][2], bq[pp][3]);
                }
        }
        __syncthreads();
    }

#pragma unroll
    for (int t = 0; t < 2; ++t)
#pragma unroll
        for (int tt = 0; tt < 8; ++tt) {
            size_t row = mtile + mwarp * 32 + t * 16 + (lane >> 2);
            int    col = ntile + nwarp * 64 + tt * 8 + (lane & 3) * 2;
            float b0 = __ldg(bias + col), b1 = __ldg(bias + col + 1);
            float2 v0 = {d[t][tt][0] + b0, d[t][tt][1] + b1};
            float2 v1 = {d[t][tt][2] + b0, d[t][tt][3] + b1};
            *reinterpret_cast<float2*>(g_xz + row * NCOL + col)       = v0;
            *reinterpret_cast<float2*>(g_xz + (row + 8) * NCOL + col) = v1;
        }
}

// ---------------- recurrent kernel: HMMA bf16 split, pipelined staging ----
#define ROFF_W 0
#define ROFF_H 49152
#define ROFF_Z 180224
#define RSMEM  (180224 + 12288)   // zb[2][64][24] fp32

__device__ __forceinline__ float fast_sigmoid(float x) {
    return 1.f / (1.f + __expf(-x));
}
__device__ __forceinline__ float fast_tanh(float x) {
    float ax = fabsf(x);
    float e  = __expf(-2.f * ax);
    float t  = (1.f - e) / (1.f + e);
    return copysignf(t, x);
}

__global__ void __launch_bounds__(256, 1)
lstm_recurrent(const float* __restrict__ W, float* __restrict__ y) {
    extern __shared__ char smem[];
    const uint32_t sb = smem_u32(smem);
    const int tid  = threadIdx.x;
    const int wid  = tid >> 5, lane = tid & 31;
    const int mw   = wid & 3;        // M-tile (rows mw*16..+15)
    const int kw   = wid >> 2;       // K-half
    const int bid  = blockIdx.x;
    const int j0   = bid * 4;

    // zero W region (incl. pad rows 20-23), then fill 20 rows hi/lo
    for (int i = tid; i < 49152 / 16; i += 256) {
        uint4 z = {0, 0, 0, 0};
        *reinterpret_cast<uint4*>(smem + ROFF_W + i * 16) = z;
    }
    __syncthreads();
    for (int idx = tid; idx < 20 * 512; idx += 256) {
        int c = idx >> 9, k = idx & 511;
        int g = c >> 2, jj = c & 3;
        float v = W[(size_t)(I_ + k) * NCOL + g * H_ + j0 + jj];
        __nv_bfloat16 hi = __float2bfloat16_rn(v);
        __nv_bfloat16 lo = __float2bfloat16_rn(v - __bfloat162float(hi));
        uint32_t X = (uint32_t)(c & 7) << 4;
        *reinterpret_cast<__nv_bfloat16*>(smem + ROFF_W + c * 2048 + ((k * 2) ^ X)) = hi;
        *reinterpret_cast<__nv_bfloat16*>(smem + ROFF_W + c * 2048 + ((1024 + k * 2) ^ X)) = lo;
    }

    // gate identity: one (b, j) per thread, c-state in register
    const int b_r  = tid >> 2;
    const int jj_r = tid & 3;
    const int j_r  = j0 + jj_r;
    float c_state = 0.f;

    // ldmatrix lane components
    const int rAr  = mw * 16 + (lane & 15);
    const int kbA  = (lane & 16) ? 16 : 0;
    const uint32_t XA = (uint32_t)(rAr & 7) << 4;
    const uint32_t aRowHi = sb + ROFF_H + (uint32_t)rAr * 1024;
    const uint32_t aRowLo = aRowHi + 65536;

    const int nB4  = ((lane >> 4) << 3) + (lane & 7);
    const int kbB4 = (lane & 8) ? 16 : 0;
    const uint32_t XB4 = (uint32_t)(nB4 & 7) << 4;
    const uint32_t b4Row = sb + ROFF_W + (uint32_t)nB4 * 2048;

    const int nB2  = 16 + (lane & 7);
    const int kbB2 = (lane & 8) ? 16 : 0;
    const uint32_t XB2 = (uint32_t)(nB2 & 7) << 4;
    const uint32_t b2Row = sb + ROFF_W + (uint32_t)nB2 * 2048;

    float* zb0 = reinterpret_cast<float*>(smem + ROFF_Z);          // kw==0
    float* zb1 = reinterpret_cast<float*>(smem + ROFF_Z + 6144);   // kw==1
    float* zbw = kw ? zb1 : zb0;
    const int rrow = mw * 16 + (lane >> 2);
    const int rcol = (lane & 3) * 2;

    __syncthreads();

    for (int s = 0; s < S_; ++s) {
        const int pp = s & 1;

        // prefetch xz gate pre-activations (DRAM, hidden behind staging+MMA)
        float xzv[5];
        {
            const float* xp = g_xz + ((size_t)s * B_ + b_r) * NCOL + j_r;
#pragma unroll
            for (int g = 0; g < 5; ++g) xzv[g] = __ldg(xp + g * H_);
        }

        // stage h: hi group first (64KB), then lo group (64KB)
        {
            const uint4* hsrc = reinterpret_cast<const uint4*>(&g_hb[pp][0][0]);
#pragma unroll 4
            for (int q = tid; q < 4096; q += 256) {          // hi
                int b = q >> 6, k8 = q & 63;
                uint32_t off = (uint32_t)b * 1024 +
                               (((uint32_t)k8 * 16) ^ ((uint32_t)(b & 7) << 4));
                cpa16(sb + ROFF_H + off, hsrc + q);
            }
            CPA_COMMIT();
#pragma unroll 4
            for (int q = tid; q < 4096; q += 256) {          // lo
                int b = q >> 6, k8 = q & 63;
                uint32_t off = 65536 + (uint32_t)b * 1024 +
                               (((uint32_t)k8 * 16) ^ ((uint32_t)(b & 7) << 4));
                cpa16(sb + ROFF_H + off, hsrc + 4096 + q);
            }
            CPA_COMMIT();
        }

        float acc[3][4];
#pragma unroll
        for (int t = 0; t < 3; ++t)
#pragma unroll
            for (int q = 0; q < 4; ++q) acc[t][q] = 0.f;

        // ---- phase A: h_hi · (W_hi and W_lo); shared A operand ----
        CPA_WAIT(1);            // hi group complete (lo may still be in flight)
        __syncthreads();
#pragma unroll 4
        for (int st = 0; st < 16; ++st) {
            uint32_t kb = (uint32_t)kw * 512 + (uint32_t)st * 32;
            uint32_t a[4], bh01[4], bh2[2], bl01[4], bl2[2];
            ldmx4(a,    aRowHi + ((kb + kbA) ^ XA));
            ldmx4(bh01, b4Row + ((kb + kbB4) ^ XB4));
            ldmx2(bh2,  b2Row + ((kb + kbB2) ^ XB2));
            ldmx4(bl01, b4Row + ((1024 + kb + kbB4) ^ XB4));
            ldmx2(bl2,  b2Row + ((1024 + kb + kbB2) ^ XB2));
            mma_bf16(acc[0], a, bh01[0], bh01[1]);
            mma_bf16(acc[1], a, bh01[2], bh01[3]);
            mma_bf16(acc[2], a, bh2[0], bh2[1]);
            mma_bf16(acc[0], a, bl01[0], bl01[1]);
            mma_bf16(acc[1], a, bl01[2], bl01[3]);
            mma_bf16(acc[2], a, bl2[0], bl2[1]);
        }

        // ---- phase B: h_lo · W_hi ----
        CPA_WAIT(0);
        __syncthreads();
#pragma unroll 4
        for (int st = 0; st < 16; ++st) {
            uint32_t kb = (uint32_t)kw * 512 + (uint32_t)st * 32;
            uint32_t a[4], bh01[4], bh2[2];
            ldmx4(a,    aRowLo + ((kb + kbA) ^ XA));
            ldmx4(bh01, b4Row + ((kb + kbB4) ^ XB4));
            ldmx2(bh2,  b2Row + ((kb + kbB2) ^ XB2));
            mma_bf16(acc[0], a, bh01[0], bh01[1]);
            mma_bf16(acc[1], a, bh01[2], bh01[3]);
            mma_bf16(acc[2], a, bh2[0], bh2[1]);
        }

        // K-reduction: each kw half writes its own region; single sync
#pragma unroll
        for (int t = 0; t < 3; ++t) {
            zbw[rrow * 24 + t * 8 + rcol]           = acc[t][0];
            zbw[rrow * 24 + t * 8 + rcol + 1]       = acc[t][1];
            zbw[(rrow + 8) * 24 + t * 8 + rcol]     = acc[t][2];
            zbw[(rrow + 8) * 24 + t * 8 + rcol + 1] = acc[t][3];
        }
        __syncthreads();

        // gates
        float z[5];
#pragma unroll
        for (int g = 0; g < 5; ++g)
            z[g] = zb0[b_r * 24 + g * 4 + jj_r] + zb1[b_r * 24 + g * 4 + jj_r] + xzv[g];
        float it = fast_sigmoid(z[0]);
        float ft = fast_sigmoid(z[1]);
        float ot = fast_sigmoid(z[2]);
        float tc = fast_tanh(z[3]);
        float dt = fast_tanh(z[4]);
        float cp = ft * c_state + it * tc;
        float cn = cp + dt * (cp - c_state);   // highway update
        c_state = cn;
        float hn = ot * fast_tanh(cn);

        // h store FIRST (critical path), publish, then y store off-path
        {
            __nv_bfloat16 hi = __float2bfloat16_rn(hn);
            __nv_bfloat16 lo = __float2bfloat16_rn(hn - __bfloat162float(hi));
            g_hb[pp ^ 1][0][b_r * H_ + j_r] = hi;
            g_hb[pp ^ 1][1][b_r * H_ + j_r] = lo;
        }
        __syncthreads();                     // all h stores done CTA-wide
        if (tid == 0) st_rel(&g_arrive[bid], (unsigned)(s + 1));

        y[((size_t)b_r * S_ + s) * H_ + j_r] = hn;

        // pure-spin acquire barrier
        if (tid < NBLK) {
            const unsigned tgt = (unsigned)(s + 1);
            while (ld_acq(&g_arrive[tid]) < tgt) { }
        }
        __syncthreads();
    }
}

// ---------------- launch (lstm_recurrent is the 4th launch -> ncu target) --
extern "C" void kernel_launch(void* const* d_in, const int* in_sizes, int n_in,
                              void* d_out, int out_size) {
    const float* x    = (const float*)d_in[0];  // [B,S,I]
    const float* W    = (const float*)d_in[1];  // [I+H, 5H]
    const float* bias = (const float*)d_in[2];  // [5H]
    float* y = (float*)d_out;                   // [B,S,H]

    cudaFuncSetAttribute(lstm_recurrent,
                         cudaFuncAttributeMaxDynamicSharedMemorySize, RSMEM);
    cudaFuncSetAttribute(gemm_mma,
                         cudaFuncAttributeMaxDynamicSharedMemorySize, GEMM_SMEM);

    convert_x<<<65536, 256>>>(x);               // 1 (includes state init)
    convert_w<<<5120, 256>>>(W);                // 2

    dim3 grid(NCOL / 128, (B_ * (size_t)S_) / 128);   // (20, 1024)
    gemm_mma<<<grid, 256, GEMM_SMEM>>>(bias);   // 3

    lstm_recurrent<<<NBLK, 256, RSMEM>>>(W, y); // 4  <- profiled slot
}

// round 6
// speedup vs baseline: 2.9335x; 1.7638x over previous
#include <cuda_runtime.h>
#include <cuda_bf16.h>
#include <cstdint>
#include <cstddef>

#define B_    64
#define S_    2048
#define I_    512
#define H_    512
#define NCOL  2560   // 5*H
#define NBLK  128    // persistent blocks for recurrence

// ---------------- device scratch (no allocations allowed) ----------------
__device__ float          g_xz[335544320];       // [S*B][5H] fp32
__device__ __nv_bfloat16  g_hb[2][2][B_ * H_];   // [pingpong][hi/lo][b*512+j]
__device__ unsigned       g_arrive[NBLK * 32];   // barrier flags, 128B stride
__device__ __nv_bfloat16  g_xhi[67108864];       // [S*B][512] bf16 hi
__device__ __nv_bfloat16  g_xlo[67108864];       // [S*B][512] bf16 lo
__device__ __nv_bfloat16  g_wthi[NCOL * 512];    // W[0:512][:] transposed [n][k]
__device__ __nv_bfloat16  g_wtlo[NCOL * 512];

// ---------------- PTX helpers (baseline PTX only, no sm_103a features) ----
__device__ __forceinline__ uint32_t smem_u32(const void* p) {
    uint32_t a;
    asm("{ .reg .u64 t; cvta.to.shared.u64 t, %1; cvt.u32.u64 %0, t; }" : "=r"(a) : "l"(p));
    return a;
}
__device__ __forceinline__ void ldmx4(uint32_t* r, uint32_t addr) {
    asm volatile("ldmatrix.sync.aligned.m8n8.x4.shared.b16 {%0,%1,%2,%3}, [%4];"
                 : "=r"(r[0]), "=r"(r[1]), "=r"(r[2]), "=r"(r[3]) : "r"(addr));
}
__device__ __forceinline__ void ldmx2(uint32_t* r, uint32_t addr) {
    asm volatile("ldmatrix.sync.aligned.m8n8.x2.shared.b16 {%0,%1}, [%2];"
                 : "=r"(r[0]), "=r"(r[1]) : "r"(addr));
}
__device__ __forceinline__ void mma_bf16(float* d, const uint32_t* a,
                                         uint32_t b0, uint32_t b1) {
    asm volatile("mma.sync.aligned.m16n8k16.row.col.f32.bf16.bf16.f32 "
                 "{%0,%1,%2,%3}, {%4,%5,%6,%7}, {%8,%9}, {%0,%1,%2,%3};"
                 : "+f"(d[0]), "+f"(d[1]), "+f"(d[2]), "+f"(d[3])
                 : "r"(a[0]), "r"(a[1]), "r"(a[2]), "r"(a[3]), "r"(b0), "r"(b1));
}
__device__ __forceinline__ void cpa16(uint32_t saddr, const void* g) {
    asm volatile("cp.async.cg.shared.global [%0], [%1], 16;" :: "r"(saddr), "l"(g));
}
#define CPA_COMMIT() asm volatile("cp.async.commit_group;" ::: "memory")
#define CPA_WAIT(n)  asm volatile("cp.async.wait_group %0;" :: "n"(n) : "memory")

__device__ __forceinline__ unsigned ld_acq(const unsigned* p) {
    unsigned v;
    asm volatile("ld.acquire.gpu.global.u32 %0, [%1];" : "=r"(v) : "l"(p) : "memory");
    return v;
}
__device__ __forceinline__ void st_rel(unsigned* p, unsigned v) {
    asm volatile("st.release.gpu.global.u32 [%0], %1;" :: "l"(p), "r"(v) : "memory");
}

// ---------------- bf16 split conversions (+ state init merged in) --------
__global__ void convert_x(const float* __restrict__ X) {
    // merged init: first 128 blocks zero h0 ping-pong + spread barrier flags
    if (blockIdx.x < 128) {
        int idx = blockIdx.x * 256 + threadIdx.x;   // 32768 = g_hb[0] in u32
        reinterpret_cast<uint32_t*>(g_hb)[idx] = 0u;
        if (idx < NBLK * 32) g_arrive[idx] = 0u;
    }
    size_t i = (size_t)blockIdx.x * 256 + threadIdx.x;
    size_t row = i >> 7;
    int    k4  = (int)(i & 127) << 2;
    int    s = (int)(row >> 6), b = (int)(row & 63);
    float4 v = *reinterpret_cast<const float4*>(X + ((size_t)b * S_ + s) * I_ + k4);
    union { __nv_bfloat16 h[4]; uint2 u; } Hh, Ll;
    float f[4] = {v.x, v.y, v.z, v.w};
#pragma unroll
    for (int j = 0; j < 4; ++j) {
        Hh.h[j] = __float2bfloat16_rn(f[j]);
        Ll.h[j] = __float2bfloat16_rn(f[j] - __bfloat162float(Hh.h[j]));
    }
    *reinterpret_cast<uint2*>(g_xhi + row * I_ + k4) = Hh.u;
    *reinterpret_cast<uint2*>(g_xlo + row * I_ + k4) = Ll.u;
}

__global__ void convert_w(const float* __restrict__ W) {
    int idx = blockIdx.x * 256 + threadIdx.x;
    int n = idx >> 9, k = idx & 511;
    float v = W[(size_t)k * NCOL + n];
    __nv_bfloat16 hi = __float2bfloat16_rn(v);
    g_wthi[idx] = hi;
    g_wtlo[idx] = __float2bfloat16_rn(v - __bfloat162float(hi));
}

// ---------------- precompute GEMM: mma.sync bf16, 3-term split (frozen) --
#define GSTRIDE 80
#define GOFF_A0 0
#define GOFF_A1 10240
#define GOFF_B0 20480
#define GOFF_B1 30720
#define GEMM_SMEM 40960

__global__ void __launch_bounds__(256, 2)
gemm_mma(const float* __restrict__ bias) {
    extern __shared__ char smem[];
    const uint32_t sb = smem_u32(smem);
    const int tid = threadIdx.x;
    const int wid = tid >> 5, lane = tid & 31;
    const int mwarp = wid & 3;
    const int nwarp = wid >> 2;
    const int ntile = blockIdx.x * 128;
    const size_t mtile = (size_t)blockIdx.y * 128;

    float d[2][8][4];
#pragma unroll
    for (int t = 0; t < 2; ++t)
#pragma unroll
        for (int tt = 0; tt < 8; ++tt)
#pragma unroll
            for (int q = 0; q < 4; ++q) d[t][tt][q] = 0.f;

    const uint32_t offA[2] = {sb + GOFF_A0, sb + GOFF_A1};
    const uint32_t offB[2] = {sb + GOFF_B0, sb + GOFF_B1};

    const int rA  = mwarp * 32 + (lane & 15);
    const int kbA = (lane & 16) ? 16 : 0;
    const int nB  = nwarp * 64 + ((lane >> 4) << 3) + (lane & 7);
    const int kbB = (lane & 8) ? 16 : 0;

    const int r0s = tid >> 2,          c0s = (tid & 3);
    const int r1s = (tid + 256) >> 2,  c1s = (tid & 3);

    auto issue = [&](int it, int buf) {
        const int seg = it >> 4;
        const int kk  = (it & 15) * 32;
        const __nv_bfloat16* Asrc = (seg == 1) ? g_xlo : g_xhi;
        const __nv_bfloat16* Bsrc = (seg == 2) ? g_wtlo : g_wthi;
        cpa16(offA[buf] + r0s * GSTRIDE + c0s * 16, Asrc + (mtile + r0s) * 512 + kk + c0s * 8);
        cpa16(offA[buf] + r1s * GSTRIDE + c1s * 16, Asrc + (mtile + r1s) * 512 + kk + c1s * 8);
        cpa16(offB[buf] + r0s * GSTRIDE + c0s * 16, Bsrc + (size_t)(ntile + r0s) * 512 + kk + c0s * 8);
        cpa16(offB[buf] + r1s * GSTRIDE + c1s * 16, Bsrc + (size_t)(ntile + r1s) * 512 + kk + c1s * 8);
        CPA_COMMIT();
    };

    issue(0, 0);
    for (int it = 0; it < 48; ++it) {
        const int buf = it & 1;
        if (it + 1 < 48) { issue(it + 1, buf ^ 1); CPA_WAIT(1); }
        else             { CPA_WAIT(0); }
        __syncthreads();

        const uint32_t ab = offA[buf], bb = offB[buf];
#pragma unroll
        for (int s = 0; s < 2; ++s) {
            uint32_t a[2][4];
            ldmx4(a[0], ab + (rA +  0) * GSTRIDE + s * 32 + kbA);
            ldmx4(a[1], ab + (rA + 16) * GSTRIDE + s * 32 + kbA);
            uint32_t bq[4][4];
#pragma unroll
            for (int pp = 0; pp < 4; ++pp)
                ldmx4(bq[pp], bb + (nB + pp * 16) * GSTRIDE + s * 32 + kbB);
#pragma unroll
            for (int t = 0; t < 2; ++t)
#pragma unroll
                for (int pp = 0; pp < 4; ++pp) {
                    mma_bf16(d[t][2 * pp],     a[t], bq[pp][0], bq[pp][1]);
                    mma_bf16(d[t][2 * pp + 1], a[t], bq[pp][2], bq[pp][3]);
                }
        }
        __syncthreads();
    }

#pragma unroll
    for (int t = 0; t < 2; ++t)
#pragma unroll
        for (int tt = 0; tt < 8; ++tt) {
            size_t row = mtile + mwarp * 32 + t * 16 + (lane >> 2);
            int    col = ntile + nwarp * 64 + tt * 8 + (lane & 3) * 2;
            float b0 = __ldg(bias + col), b1 = __ldg(bias + col + 1);
            float2 v0 = {d[t][tt][0] + b0, d[t][tt][1] + b1};
            float2 v1 = {d[t][tt][2] + b0, d[t][tt][3] + b1};
            *reinterpret_cast<float2*>(g_xz + row * NCOL + col)       = v0;
            *reinterpret_cast<float2*>(g_xz + (row + 8) * NCOL + col) = v1;
        }
}

// ---------------- recurrent kernel: warp-private staging, spread flags ----
// SMEM: W [24 rows][1024 k] bf16 hi|lo, stride 2048B, swizzled   (48 KB)
//       h  per-warp A tiles: 8 warps x (8KB hi + 8KB lo)         (128 KB)
//       zb [2][64][24] fp32                                      (12 KB)
#define ROFF_W 0
#define ROFF_H 49152
#define ROFF_Z 180224
#define RSMEM  (180224 + 12288)

__device__ __forceinline__ float fast_sigmoid(float x) {
    return 1.f / (1.f + __expf(-x));
}
__device__ __forceinline__ float fast_tanh(float x) {
    float ax = fabsf(x);
    float e  = __expf(-2.f * ax);
    float t  = (1.f - e) / (1.f + e);
    return copysignf(t, x);
}

__global__ void __launch_bounds__(256, 1)
lstm_recurrent(const float* __restrict__ W, float* __restrict__ y) {
    extern __shared__ char smem[];
    const uint32_t sb = smem_u32(smem);
    const int tid  = threadIdx.x;
    const int wid  = tid >> 5, lane = tid & 31;
    const int mw   = wid & 3;        // M-tile (rows mw*16..+15)
    const int kw   = wid >> 2;       // K-half
    const int bid  = blockIdx.x;
    const int j0   = bid * 4;

    // zero W region (incl. pad rows 20-23), then fill 20 rows hi/lo
    for (int i = tid; i < 49152 / 16; i += 256) {
        uint4 z = {0, 0, 0, 0};
        *reinterpret_cast<uint4*>(smem + ROFF_W + i * 16) = z;
    }
    __syncthreads();
    for (int idx = tid; idx < 20 * 512; idx += 256) {
        int c = idx >> 9, k = idx & 511;
        int g = c >> 2, jj = c & 3;
        float v = W[(size_t)(I_ + k) * NCOL + g * H_ + j0 + jj];
        __nv_bfloat16 hi = __float2bfloat16_rn(v);
        __nv_bfloat16 lo = __float2bfloat16_rn(v - __bfloat162float(hi));
        uint32_t X = (uint32_t)(c & 7) << 4;
        *reinterpret_cast<__nv_bfloat16*>(smem + ROFF_W + c * 2048 + ((k * 2) ^ X)) = hi;
        *reinterpret_cast<__nv_bfloat16*>(smem + ROFF_W + c * 2048 + ((1024 + k * 2) ^ X)) = lo;
    }

    // gate identity: one (b, j) per thread, c-state in register
    const int b_r  = tid >> 2;
    const int jj_r = tid & 3;
    const int j_r  = j0 + jj_r;
    float c_state = 0.f;

    // warp-private A tile region: 16KB per warp (8KB hi + 8KB lo)
    const uint32_t wbase = sb + ROFF_H + (uint32_t)wid * 16384;
    const int arow0 = mw * 16;              // global h rows [arow0, arow0+16)
    const int kOff  = kw * 256;             // element offset of k-half

    // ldmatrix A lane components (local tile: 16 rows x 512B)
    const uint32_t aTileHi = wbase + (uint32_t)(lane & 15) * 512;
    const uint32_t aTileLo = aTileHi + 8192;
    const uint32_t kbA = (lane & 16) ? 16 : 0;
    const uint32_t XA2 = (uint32_t)(lane & 7) << 4;

    // ldmatrix B lane components (W region, 2KB row stride)
    const int nB4  = ((lane >> 4) << 3) + (lane & 7);
    const uint32_t kbB4 = (lane & 8) ? 16 : 0;
    const uint32_t XB4 = (uint32_t)(nB4 & 7) << 4;
    const uint32_t b4Row = sb + ROFF_W + (uint32_t)nB4 * 2048;

    const int nB2  = 16 + (lane & 7);
    const uint32_t kbB2 = (lane & 8) ? 16 : 0;
    const uint32_t XB2 = (uint32_t)(nB2 & 7) << 4;
    const uint32_t b2Row = sb + ROFF_W + (uint32_t)nB2 * 2048;

    float* zb0 = reinterpret_cast<float*>(smem + ROFF_Z);          // kw==0
    float* zb1 = reinterpret_cast<float*>(smem + ROFF_Z + 6144);   // kw==1
    float* zbw = kw ? zb1 : zb0;
    const int rrow = mw * 16 + (lane >> 2);
    const int rcol = (lane & 3) * 2;

    __syncthreads();

    for (int s = 0; s < S_; ++s) {
        const int pp = s & 1;

        // prefetch xz gate pre-activations (DRAM, hidden behind staging+MMA)
        float xzv[5];
        {
            const float* xp = g_xz + ((size_t)s * B_ + b_r) * NCOL + j_r;
#pragma unroll
            for (int g = 0; g < 5; ++g) xzv[g] = __ldg(xp + g * H_);
        }

        // warp-private staging: this warp's 16 rows x 256-k half, hi then lo
        {
            const __nv_bfloat16* hbase = &g_hb[pp][0][0];
#pragma unroll
            for (int i = 0; i < 16; ++i) {
                uint32_t dst = wbase + (uint32_t)i * 512 +
                               (((uint32_t)lane * 16) ^ ((uint32_t)(i & 7) << 4));
                cpa16(dst, hbase + (size_t)(arow0 + i) * 512 + kOff + lane * 8);
            }
            CPA_COMMIT();
#pragma unroll
            for (int i = 0; i < 16; ++i) {
                uint32_t dst = wbase + 8192 + (uint32_t)i * 512 +
                               (((uint32_t)lane * 16) ^ ((uint32_t)(i & 7) << 4));
                cpa16(dst, hbase + 32768 + (size_t)(arow0 + i) * 512 + kOff + lane * 8);
            }
            CPA_COMMIT();
        }

        float acc[3][4];
#pragma unroll
        for (int t = 0; t < 3; ++t)
#pragma unroll
            for (int q = 0; q < 4; ++q) acc[t][q] = 0.f;

        // ---- phase A: h_hi · (W_hi and W_lo); warp-local wait only ----
        CPA_WAIT(1);
        __syncwarp();
#pragma unroll 4
        for (int st = 0; st < 16; ++st) {
            uint32_t kb  = (uint32_t)st * 32;            // local A k-bytes
            uint32_t kbw = (uint32_t)kw * 512 + kb;      // W k-bytes
            uint32_t a[4], bh01[4], bh2[2], bl01[4], bl2[2];
            ldmx4(a,    aTileHi + ((kb + kbA) ^ XA2));
            ldmx4(bh01, b4Row + ((kbw + kbB4) ^ XB4));
            ldmx2(bh2,  b2Row + ((kbw + kbB2) ^ XB2));
            ldmx4(bl01, b4Row + ((1024 + kbw + kbB4) ^ XB4));
            ldmx2(bl2,  b2Row + ((1024 + kbw + kbB2) ^ XB2));
            mma_bf16(acc[0], a, bh01[0], bh01[1]);
            mma_bf16(acc[1], a, bh01[2], bh01[3]);
            mma_bf16(acc[2], a, bh2[0], bh2[1]);
            mma_bf16(acc[0], a, bl01[0], bl01[1]);
            mma_bf16(acc[1], a, bl01[2], bl01[3]);
            mma_bf16(acc[2], a, bl2[0], bl2[1]);
        }

        // ---- phase B: h_lo · W_hi ----
        CPA_WAIT(0);
        __syncwarp();
#pragma unroll 4
        for (int st = 0; st < 16; ++st) {
            uint32_t kb  = (uint32_t)st * 32;
            uint32_t kbw = (uint32_t)kw * 512 + kb;
            uint32_t a[4], bh01[4], bh2[2];
            ldmx4(a,    aTileLo + ((kb + kbA) ^ XA2));
            ldmx4(bh01, b4Row + ((kbw + kbB4) ^ XB4));
            ldmx2(bh2,  b2Row + ((kbw + kbB2) ^ XB2));
            mma_bf16(acc[0], a, bh01[0], bh01[1]);
            mma_bf16(acc[1], a, bh01[2], bh01[3]);
            mma_bf16(acc[2], a, bh2[0], bh2[1]);
        }

        // K-reduction: each kw half writes its own region; single sync
#pragma unroll
        for (int t = 0; t < 3; ++t) {
            zbw[rrow * 24 + t * 8 + rcol]           = acc[t][0];
            zbw[rrow * 24 + t * 8 + rcol + 1]       = acc[t][1];
            zbw[(rrow + 8) * 24 + t * 8 + rcol]     = acc[t][2];
            zbw[(rrow + 8) * 24 + t * 8 + rcol + 1] = acc[t][3];
        }
        __syncthreads();

        // gates
        float z[5];
#pragma unroll
        for (int g = 0; g < 5; ++g)
            z[g] = zb0[b_r * 24 + g * 4 + jj_r] + zb1[b_r * 24 + g * 4 + jj_r] + xzv[g];
        float it = fast_sigmoid(z[0]);
        float ft = fast_sigmoid(z[1]);
        float ot = fast_sigmoid(z[2]);
        float tc = fast_tanh(z[3]);
        float dt = fast_tanh(z[4]);
        float cp = ft * c_state + it * tc;
        float cn = cp + dt * (cp - c_state);   // highway update
        c_state = cn;
        float hn = ot * fast_tanh(cn);

        // h store FIRST (critical path), publish, then y store off-path
        {
            __nv_bfloat16 hi = __float2bfloat16_rn(hn);
            __nv_bfloat16 lo = __float2bfloat16_rn(hn - __bfloat162float(hi));
            g_hb[pp ^ 1][0][b_r * H_ + j_r] = hi;
            g_hb[pp ^ 1][1][b_r * H_ + j_r] = lo;
        }
        __syncthreads();                     // all h stores done CTA-wide
        if (tid == 0) st_rel(&g_arrive[bid * 32], (unsigned)(s + 1));

        y[((size_t)b_r * S_ + s) * H_ + j_r] = hn;

        // spread-flag spin barrier: 1 flag per 128B line
        if (tid < NBLK) {
            const unsigned tgt = (unsigned)(s + 1);
            while (ld_acq(&g_arrive[tid * 32]) < tgt) { }
        }
        __syncthreads();
    }
}

// ---------------- launch (lstm_recurrent is the 4th launch -> ncu target) --
extern "C" void kernel_launch(void* const* d_in, const int* in_sizes, int n_in,
                              void* d_out, int out_size) {
    const float* x    = (const float*)d_in[0];  // [B,S,I]
    const float* W    = (const float*)d_in[1];  // [I+H, 5H]
    const float* bias = (const float*)d_in[2];  // [5H]
    float* y = (float*)d_out;                   // [B,S,H]

    cudaFuncSetAttribute(lstm_recurrent,
                         cudaFuncAttributeMaxDynamicSharedMemorySize, RSMEM);
    cudaFuncSetAttribute(gemm_mma,
                         cudaFuncAttributeMaxDynamicSharedMemorySize, GEMM_SMEM);

    convert_x<<<65536, 256>>>(x);               // 1 (includes state init)
    convert_w<<<5120, 256>>>(W);                // 2

    dim3 grid(NCOL / 128, (B_ * (size_t)S_) / 128);   // (20, 1024)
    gemm_mma<<<grid, 256, GEMM_SMEM>>>(bias);   // 3

    lstm_recurrent<<<NBLK, 256, RSMEM>>>(W, y); // 4  <- profiled slot
}

// round 7
// speedup vs baseline: 3.4298x; 1.1692x over previous
#include <cuda_runtime.h>
#include <cuda_bf16.h>
#include <cstdint>
#include <cstddef>

#define B_    64
#define S_    2048
#define I_    512
#define H_    512
#define NCOL  2560   // 5*H
#define NBLK  128    // persistent blocks for recurrence

// ---------------- device scratch (no allocations allowed) ----------------
__device__ float          g_xz[335544320];       // [S*B][5H] fp32
__device__ __nv_bfloat16  g_hb[2][2][B_ * H_];   // [pingpong][hi/lo][b*512+j]
__device__ unsigned       g_counter;             // barrier arrival counter
__device__ __nv_bfloat16  g_xhi[67108864];       // [S*B][512] bf16 hi
__device__ __nv_bfloat16  g_xlo[67108864];       // [S*B][512] bf16 lo
__device__ __nv_bfloat16  g_wthi[NCOL * 512];    // W[0:512][:] transposed [n][k]
__device__ __nv_bfloat16  g_wtlo[NCOL * 512];

// ---------------- PTX helpers (baseline PTX only, no sm_103a features) ----
__device__ __forceinline__ uint32_t smem_u32(const void* p) {
    uint32_t a;
    asm("{ .reg .u64 t; cvta.to.shared.u64 t, %1; cvt.u32.u64 %0, t; }" : "=r"(a) : "l"(p));
    return a;
}
__device__ __forceinline__ void ldmx4(uint32_t* r, uint32_t addr) {
    asm volatile("ldmatrix.sync.aligned.m8n8.x4.shared.b16 {%0,%1,%2,%3}, [%4];"
                 : "=r"(r[0]), "=r"(r[1]), "=r"(r[2]), "=r"(r[3]) : "r"(addr));
}
__device__ __forceinline__ void ldmx2(uint32_t* r, uint32_t addr) {
    asm volatile("ldmatrix.sync.aligned.m8n8.x2.shared.b16 {%0,%1}, [%2];"
                 : "=r"(r[0]), "=r"(r[1]) : "r"(addr));
}
__device__ __forceinline__ void mma_bf16(float* d, const uint32_t* a,
                                         uint32_t b0, uint32_t b1) {
    asm volatile("mma.sync.aligned.m16n8k16.row.col.f32.bf16.bf16.f32 "
                 "{%0,%1,%2,%3}, {%4,%5,%6,%7}, {%8,%9}, {%0,%1,%2,%3};"
                 : "+f"(d[0]), "+f"(d[1]), "+f"(d[2]), "+f"(d[3])
                 : "r"(a[0]), "r"(a[1]), "r"(a[2]), "r"(a[3]), "r"(b0), "r"(b1));
}
__device__ __forceinline__ void cpa16(uint32_t saddr, const void* g) {
    asm volatile("cp.async.cg.shared.global [%0], [%1], 16;" :: "r"(saddr), "l"(g));
}
#define CPA_COMMIT() asm volatile("cp.async.commit_group;" ::: "memory")
#define CPA_WAIT(n)  asm volatile("cp.async.wait_group %0;" :: "n"(n) : "memory")

__device__ __forceinline__ unsigned ld_acq(const unsigned* p) {
    unsigned v;
    asm volatile("ld.acquire.gpu.global.u32 %0, [%1];" : "=r"(v) : "l"(p) : "memory");
    return v;
}
__device__ __forceinline__ void red_add_rel(unsigned* p, unsigned v) {
    asm volatile("red.release.gpu.global.add.u32 [%0], %1;" :: "l"(p), "r"(v) : "memory");
}

// ---------------- bf16 split conversions (+ state init merged in) --------
__global__ void convert_x(const float* __restrict__ X) {
    // merged init: first 128 blocks zero h0 ping-pong; block 0 zeroes counter
    if (blockIdx.x < 128) {
        int idx = blockIdx.x * 256 + threadIdx.x;   // 32768 = g_hb[0] in u32
        reinterpret_cast<uint32_t*>(g_hb)[idx] = 0u;
        if (blockIdx.x == 0 && threadIdx.x == 0) g_counter = 0u;
    }
    size_t i = (size_t)blockIdx.x * 256 + threadIdx.x;
    size_t row = i >> 7;
    int    k4  = (int)(i & 127) << 2;
    int    s = (int)(row >> 6), b = (int)(row & 63);
    float4 v = *reinterpret_cast<const float4*>(X + ((size_t)b * S_ + s) * I_ + k4);
    union { __nv_bfloat16 h[4]; uint2 u; } Hh, Ll;
    float f[4] = {v.x, v.y, v.z, v.w};
#pragma unroll
    for (int j = 0; j < 4; ++j) {
        Hh.h[j] = __float2bfloat16_rn(f[j]);
        Ll.h[j] = __float2bfloat16_rn(f[j] - __bfloat162float(Hh.h[j]));
    }
    *reinterpret_cast<uint2*>(g_xhi + row * I_ + k4) = Hh.u;
    *reinterpret_cast<uint2*>(g_xlo + row * I_ + k4) = Ll.u;
}

__global__ void convert_w(const float* __restrict__ W) {
    int idx = blockIdx.x * 256 + threadIdx.x;
    int n = idx >> 9, k = idx & 511;
    float v = W[(size_t)k * NCOL + n];
    __nv_bfloat16 hi = __float2bfloat16_rn(v);
    g_wthi[idx] = hi;
    g_wtlo[idx] = __float2bfloat16_rn(v - __bfloat162float(hi));
}

// ---------------- precompute GEMM: mma.sync bf16, 3-stage pipeline -------
#define GSTRIDE 80
#define GEMM_SMEM 61440   // 3 x (A 10240 + B 10240)

__global__ void __launch_bounds__(256, 2)
gemm_mma(const float* __restrict__ bias) {
    extern __shared__ char smem[];
    const uint32_t sb = smem_u32(smem);
    const int tid = threadIdx.x;
    const int wid = tid >> 5, lane = tid & 31;
    const int mwarp = wid & 3;
    const int nwarp = wid >> 2;
    const int ntile = blockIdx.x * 128;
    const size_t mtile = (size_t)blockIdx.y * 128;

    float d[2][8][4];
#pragma unroll
    for (int t = 0; t < 2; ++t)
#pragma unroll
        for (int tt = 0; tt < 8; ++tt)
#pragma unroll
            for (int q = 0; q < 4; ++q) d[t][tt][q] = 0.f;

    const uint32_t offA[3] = {sb,          sb + 10240, sb + 20480};
    const uint32_t offB[3] = {sb + 30720,  sb + 40960, sb + 51200};

    const int rA  = mwarp * 32 + (lane & 15);
    const int kbA = (lane & 16) ? 16 : 0;
    const int nB  = nwarp * 64 + ((lane >> 4) << 3) + (lane & 7);
    const int kbB = (lane & 8) ? 16 : 0;

    const int r0s = tid >> 2,          c0s = (tid & 3);
    const int r1s = (tid + 256) >> 2,  c1s = (tid & 3);

    auto issue = [&](int it) {
        const int buf = it % 3;
        const int seg = it >> 4;
        const int kk  = (it & 15) * 32;
        const __nv_bfloat16* Asrc = (seg == 1) ? g_xlo : g_xhi;
        const __nv_bfloat16* Bsrc = (seg == 2) ? g_wtlo : g_wthi;
        cpa16(offA[buf] + r0s * GSTRIDE + c0s * 16, Asrc + (mtile + r0s) * 512 + kk + c0s * 8);
        cpa16(offA[buf] + r1s * GSTRIDE + c1s * 16, Asrc + (mtile + r1s) * 512 + kk + c1s * 8);
        cpa16(offB[buf] + r0s * GSTRIDE + c0s * 16, Bsrc + (size_t)(ntile + r0s) * 512 + kk + c0s * 8);
        cpa16(offB[buf] + r1s * GSTRIDE + c1s * 16, Bsrc + (size_t)(ntile + r1s) * 512 + kk + c1s * 8);
        CPA_COMMIT();
    };

    issue(0);
    issue(1);
    for (int it = 0; it < 48; ++it) {
        const int buf = it % 3;
        if (it < 47) { CPA_WAIT(1); } else { CPA_WAIT(0); }
        __syncthreads();
        if (it + 2 < 48) issue(it + 2);

        const uint32_t ab = offA[buf], bb = offB[buf];
#pragma unroll
        for (int s = 0; s < 2; ++s) {
            uint32_t a[2][4];
            ldmx4(a[0], ab + (rA +  0) * GSTRIDE + s * 32 + kbA);
            ldmx4(a[1], ab + (rA + 16) * GSTRIDE + s * 32 + kbA);
            uint32_t bq[4][4];
#pragma unroll
            for (int pp = 0; pp < 4; ++pp)
                ldmx4(bq[pp], bb + (nB + pp * 16) * GSTRIDE + s * 32 + kbB);
#pragma unroll
            for (int t = 0; t < 2; ++t)
#pragma unroll
                for (int pp = 0; pp < 4; ++pp) {
                    mma_bf16(d[t][2 * pp],     a[t], bq[pp][0], bq[pp][1]);
                    mma_bf16(d[t][2 * pp + 1], a[t], bq[pp][2], bq[pp][3]);
                }
        }
    }

#pragma unroll
    for (int t = 0; t < 2; ++t)
#pragma unroll
        for (int tt = 0; tt < 8; ++tt) {
            size_t row = mtile + mwarp * 32 + t * 16 + (lane >> 2);
            int    col = ntile + nwarp * 64 + tt * 8 + (lane & 3) * 2;
            float b0 = __ldg(bias + col), b1 = __ldg(bias + col + 1);
            float2 v0 = {d[t][tt][0] + b0, d[t][tt][1] + b1};
            float2 v1 = {d[t][tt][2] + b0, d[t][tt][3] + b1};
            *reinterpret_cast<float2*>(g_xz + row * NCOL + col)       = v0;
            *reinterpret_cast<float2*>(g_xz + (row + 8) * NCOL + col) = v1;
        }
}

// ---------------- recurrent kernel: W_hi in registers, counter barrier ----
// SMEM: W [24 rows][1024 k] bf16 hi|lo, stride 2048B, swizzled   (48 KB)
//       h  per-warp A tiles: 8 warps x (8KB hi + 8KB lo)         (128 KB)
//       zb [2][64][24] fp32                                      (12 KB)
#define ROFF_W 0
#define ROFF_H 49152
#define ROFF_Z 180224
#define RSMEM  (180224 + 12288)

__device__ __forceinline__ float fast_sigmoid(float x) {
    return 1.f / (1.f + __expf(-x));
}
__device__ __forceinline__ float fast_tanh(float x) {
    float ax = fabsf(x);
    float e  = __expf(-2.f * ax);
    float t  = (1.f - e) / (1.f + e);
    return copysignf(t, x);
}

__global__ void __launch_bounds__(256, 1)
lstm_recurrent(const float* __restrict__ W, float* __restrict__ y) {
    extern __shared__ char smem[];
    const uint32_t sb = smem_u32(smem);
    const int tid  = threadIdx.x;
    const int wid  = tid >> 5, lane = tid & 31;
    const int mw   = wid & 3;        // M-tile (rows mw*16..+15)
    const int kw   = wid >> 2;       // K-half
    const int bid  = blockIdx.x;
    const int j0   = bid * 4;

    // zero W region (incl. pad rows 20-23), then fill 20 rows hi/lo
    for (int i = tid; i < 49152 / 16; i += 256) {
        uint4 z = {0, 0, 0, 0};
        *reinterpret_cast<uint4*>(smem + ROFF_W + i * 16) = z;
    }
    __syncthreads();
    for (int idx = tid; idx < 20 * 512; idx += 256) {
        int c = idx >> 9, k = idx & 511;
        int g = c >> 2, jj = c & 3;
        float v = W[(size_t)(I_ + k) * NCOL + g * H_ + j0 + jj];
        __nv_bfloat16 hi = __float2bfloat16_rn(v);
        __nv_bfloat16 lo = __float2bfloat16_rn(v - __bfloat162float(hi));
        uint32_t X = (uint32_t)(c & 7) << 4;
        *reinterpret_cast<__nv_bfloat16*>(smem + ROFF_W + c * 2048 + ((k * 2) ^ X)) = hi;
        *reinterpret_cast<__nv_bfloat16*>(smem + ROFF_W + c * 2048 + ((1024 + k * 2) ^ X)) = lo;
    }

    // gate identity: one (b, j) per thread, c-state in register
    const int b_r  = tid >> 2;
    const int jj_r = tid & 3;
    const int j_r  = j0 + jj_r;
    float c_state = 0.f;

    // warp-private A tile region: 16KB per warp (8KB hi + 8KB lo)
    const uint32_t wbase = sb + ROFF_H + (uint32_t)wid * 16384;
    const int arow0 = mw * 16;              // global h rows [arow0, arow0+16)
    const int kOff  = kw * 256;             // element offset of k-half

    // ldmatrix A lane components (local tile: 16 rows x 512B)
    const uint32_t aTileHi = wbase + (uint32_t)(lane & 15) * 512;
    const uint32_t aTileLo = aTileHi + 8192;
    const uint32_t kbA = (lane & 16) ? 16 : 0;
    const uint32_t XA2 = (uint32_t)(lane & 7) << 4;

    // ldmatrix B lane components (W region, 2KB row stride)
    const int nB4  = ((lane >> 4) << 3) + (lane & 7);
    const uint32_t kbB4 = (lane & 8) ? 16 : 0;
    const uint32_t XB4 = (uint32_t)(nB4 & 7) << 4;
    const uint32_t b4Row = sb + ROFF_W + (uint32_t)nB4 * 2048;

    const int nB2  = 16 + (lane & 7);
    const uint32_t kbB2 = (lane & 8) ? 16 : 0;
    const uint32_t XB2 = (uint32_t)(nB2 & 7) << 4;
    const uint32_t b2Row = sb + ROFF_W + (uint32_t)nB2 * 2048;

    float* zb0 = reinterpret_cast<float*>(smem + ROFF_Z);          // kw==0
    float* zb1 = reinterpret_cast<float*>(smem + ROFF_Z + 6144);   // kw==1
    float* zbw = kw ? zb1 : zb0;
    const int rrow = mw * 16 + (lane >> 2);
    const int rcol = (lane & 3) * 2;

    __syncthreads();

    // ---- hoist W_hi fragments into registers (invariant across steps) ----
    uint32_t wh01[16][4], wh2[16][2];
#pragma unroll
    for (int st = 0; st < 16; ++st) {
        uint32_t kbw = (uint32_t)kw * 512 + (uint32_t)st * 32;
        ldmx4(wh01[st], b4Row + ((kbw + kbB4) ^ XB4));
        ldmx2(wh2[st],  b2Row + ((kbw + kbB2) ^ XB2));
    }

    for (int s = 0; s < S_; ++s) {
        const int pp = s & 1;

        // prefetch xz gate pre-activations (DRAM, hidden behind staging+MMA)
        float xzv[5];
        {
            const float* xp = g_xz + ((size_t)s * B_ + b_r) * NCOL + j_r;
#pragma unroll
            for (int g = 0; g < 5; ++g) xzv[g] = __ldg(xp + g * H_);
        }

        // warp-private staging: this warp's 16 rows x 256-k half, hi then lo
        {
            const __nv_bfloat16* hbase = &g_hb[pp][0][0];
#pragma unroll
            for (int i = 0; i < 16; ++i) {
                uint32_t dst = wbase + (uint32_t)i * 512 +
                               (((uint32_t)lane * 16) ^ ((uint32_t)(i & 7) << 4));
                cpa16(dst, hbase + (size_t)(arow0 + i) * 512 + kOff + lane * 8);
            }
            CPA_COMMIT();
#pragma unroll
            for (int i = 0; i < 16; ++i) {
                uint32_t dst = wbase + 8192 + (uint32_t)i * 512 +
                               (((uint32_t)lane * 16) ^ ((uint32_t)(i & 7) << 4));
                cpa16(dst, hbase + 32768 + (size_t)(arow0 + i) * 512 + kOff + lane * 8);
            }
            CPA_COMMIT();
        }

        float acc[3][4];
#pragma unroll
        for (int t = 0; t < 3; ++t)
#pragma unroll
            for (int q = 0; q < 4; ++q) acc[t][q] = 0.f;

        // ---- phase 1+2: h_hi·W_hi (regs) and h_hi·W_lo (LDSM) ----
        CPA_WAIT(1);
        __syncwarp();
#pragma unroll
        for (int st = 0; st < 16; ++st) {
            uint32_t kb  = (uint32_t)st * 32;            // local A k-bytes
            uint32_t kbw = (uint32_t)kw * 512 + kb;      // W k-bytes
            uint32_t a[4], bl01[4], bl2[2];
            ldmx4(a, aTileHi + ((kb + kbA) ^ XA2));
            mma_bf16(acc[0], a, wh01[st][0], wh01[st][1]);
            mma_bf16(acc[1], a, wh01[st][2], wh01[st][3]);
            mma_bf16(acc[2], a, wh2[st][0],  wh2[st][1]);
            ldmx4(bl01, b4Row + ((1024 + kbw + kbB4) ^ XB4));
            ldmx2(bl2,  b2Row + ((1024 + kbw + kbB2) ^ XB2));
            mma_bf16(acc[0], a, bl01[0], bl01[1]);
            mma_bf16(acc[1], a, bl01[2], bl01[3]);
            mma_bf16(acc[2], a, bl2[0], bl2[1]);
        }

        // ---- phase 3: h_lo·W_hi (regs) ----
        CPA_WAIT(0);
        __syncwarp();
#pragma unroll
        for (int st = 0; st < 16; ++st) {
            uint32_t kb = (uint32_t)st * 32;
            uint32_t a[4];
            ldmx4(a, aTileLo + ((kb + kbA) ^ XA2));
            mma_bf16(acc[0], a, wh01[st][0], wh01[st][1]);
            mma_bf16(acc[1], a, wh01[st][2], wh01[st][3]);
            mma_bf16(acc[2], a, wh2[st][0],  wh2[st][1]);
        }

        // K-reduction: each kw half writes its own region; single sync
#pragma unroll
        for (int t = 0; t < 3; ++t) {
            zbw[rrow * 24 + t * 8 + rcol]           = acc[t][0];
            zbw[rrow * 24 + t * 8 + rcol + 1]       = acc[t][1];
            zbw[(rrow + 8) * 24 + t * 8 + rcol]     = acc[t][2];
            zbw[(rrow + 8) * 24 + t * 8 + rcol + 1] = acc[t][3];
        }
        __syncthreads();

        // gates
        float z[5];
#pragma unroll
        for (int g = 0; g < 5; ++g)
            z[g] = zb0[b_r * 24 + g * 4 + jj_r] + zb1[b_r * 24 + g * 4 + jj_r] + xzv[g];
        float it = fast_sigmoid(z[0]);
        float ft = fast_sigmoid(z[1]);
        float ot = fast_sigmoid(z[2]);
        float tc = fast_tanh(z[3]);
        float dt = fast_tanh(z[4]);
        float cp = ft * c_state + it * tc;
        float cn = cp + dt * (cp - c_state);   // highway update
        c_state = cn;
        float hn = ot * fast_tanh(cn);

        // h store FIRST (critical path), publish, then y store off-path
        {
            __nv_bfloat16 hi = __float2bfloat16_rn(hn);
            __nv_bfloat16 lo = __float2bfloat16_rn(hn - __bfloat162float(hi));
            g_hb[pp ^ 1][0][b_r * H_ + j_r] = hi;
            g_hb[pp ^ 1][1][b_r * H_ + j_r] = lo;
        }
        __syncthreads();                     // all h stores done CTA-wide
        if (tid == 0) red_add_rel(&g_counter, 1u);

        y[((size_t)b_r * S_ + s) * H_ + j_r] = hn;

        // single-counter barrier: one poller per CTA
        if (tid == 0) {
            const unsigned tgt = (unsigned)(s + 1) << 7;   // 128*(s+1)
            while (ld_acq(&g_counter) < tgt) { }
        }
        __syncthreads();
    }
}

// ---------------- launch (lstm_recurrent is the 4th launch -> ncu target) --
extern "C" void kernel_launch(void* const* d_in, const int* in_sizes, int n_in,
                              void* d_out, int out_size) {
    const float* x    = (const float*)d_in[0];  // [B,S,I]
    const float* W    = (const float*)d_in[1];  // [I+H, 5H]
    const float* bias = (const float*)d_in[2];  // [5H]
    float* y = (float*)d_out;                   // [B,S,H]

    cudaFuncSetAttribute(lstm_recurrent,
                         cudaFuncAttributeMaxDynamicSharedMemorySize, RSMEM);
    cudaFuncSetAttribute(gemm_mma,
                         cudaFuncAttributeMaxDynamicSharedMemorySize, GEMM_SMEM);

    convert_x<<<65536, 256>>>(x);               // 1 (includes state init)
    convert_w<<<5120, 256>>>(W);                // 2

    dim3 grid(NCOL / 128, (B_ * (size_t)S_) / 128);   // (20, 1024)
    gemm_mma<<<grid, 256, GEMM_SMEM>>>(bias);   // 3

    lstm_recurrent<<<NBLK, 256, RSMEM>>>(W, y); // 4  <- profiled slot
}